// round 3
// baseline (speedup 1.0000x reference)
#include <cuda_runtime.h>
#include <math.h>

#define FDIM 256
#define HDIM 256
#define NCOLS 512          // [A(256) | B(256)] per node
#define MAXN 10000

__device__ float g_AB[(size_t)MAXN * NCOLS];

// ----------------------------------------------------------------------------
// Kernel 1: node projection GEMM (NT form, both operands K-contiguous)
// C[n][j] = sum_k X[n][k] * Wrow_j[k] + bias(j)
//   j <  256: Wrow_j = W1[j][0:256],   bias = b1[j]   (A part, b1 folded in)
//   j >= 256: Wrow_j = W1[j-256][256:512], bias = 0   (B part)
// ----------------------------------------------------------------------------
#define BM 64
#define BN 64
#define BK 16

__global__ __launch_bounds__(256) void node_gemm(
    const float* __restrict__ X,
    const float* __restrict__ W1,
    const float* __restrict__ b1,
    int nrows)
{
    __shared__ float As[BK][BM];
    __shared__ float Bs[BK][BN];

    const int tid = threadIdx.x;         // 0..255
    const int tx  = tid & 15;            // 0..15
    const int ty  = tid >> 4;            // 0..15
    const int m0  = blockIdx.y * BM;
    const int n0  = blockIdx.x * BN;

    const int lm  = tid >> 2;            // 0..63  (row within tile for loads)
    const int lk4 = (tid & 3) << 2;      // 0,4,8,12 (k-vector offset)

    float acc[4][4] = {};

    for (int k0 = 0; k0 < FDIM; k0 += BK) {
        // --- load X tile (transposed into As[k][m]) ---
        float4 xa = make_float4(0.f, 0.f, 0.f, 0.f);
        const int gm = m0 + lm;
        if (gm < nrows)
            xa = *(const float4*)(X + (size_t)gm * FDIM + k0 + lk4);
        As[lk4 + 0][lm] = xa.x;
        As[lk4 + 1][lm] = xa.y;
        As[lk4 + 2][lm] = xa.z;
        As[lk4 + 3][lm] = xa.w;

        // --- load W tile (transposed into Bs[k][j]) ---
        const int j = n0 + lm;
        const float* wrow = (j < HDIM)
            ? (W1 + (size_t)j * (2 * FDIM))
            : (W1 + (size_t)(j - HDIM) * (2 * FDIM) + FDIM);
        float4 wb = *(const float4*)(wrow + k0 + lk4);
        Bs[lk4 + 0][lm] = wb.x;
        Bs[lk4 + 1][lm] = wb.y;
        Bs[lk4 + 2][lm] = wb.z;
        Bs[lk4 + 3][lm] = wb.w;

        __syncthreads();

        #pragma unroll
        for (int k = 0; k < BK; ++k) {
            float4 a = *(const float4*)&As[k][ty * 4];
            float4 b = *(const float4*)&Bs[k][tx * 4];
            float av[4] = {a.x, a.y, a.z, a.w};
            float bv[4] = {b.x, b.y, b.z, b.w};
            #pragma unroll
            for (int i = 0; i < 4; ++i)
                #pragma unroll
                for (int jj = 0; jj < 4; ++jj)
                    acc[i][jj] = fmaf(av[i], bv[jj], acc[i][jj]);
        }
        __syncthreads();
    }

    // --- epilogue: add bias (b1 folded into A half), store to scratch ---
    #pragma unroll
    for (int i = 0; i < 4; ++i) {
        const int gm = m0 + ty * 4 + i;
        if (gm >= nrows) continue;
        #pragma unroll
        for (int jj = 0; jj < 4; ++jj) {
            const int gj = n0 + tx * 4 + jj;
            const float bias = (gj < HDIM) ? b1[gj] : 0.f;
            g_AB[(size_t)gm * NCOLS + gj] = acc[i][jj] + bias;
        }
    }
}

// ----------------------------------------------------------------------------
// Kernel 2: per-edge pass. One warp per edge.
//   h = relu(A[row] + B[col])          (b1 already folded into A)
//   out = sigmoid(h . W2 + b2)
// A/B rows gathered from g_AB (20.5 MB -> resident in L2 after first wave).
// NOTE: edge_index arrives as int32 (harness downcasts the reference's int64).
// ----------------------------------------------------------------------------
__global__ __launch_bounds__(256) void edge_kernel(
    const int* __restrict__ ei,
    const float* __restrict__ W2,
    const float* __restrict__ b2,
    float* __restrict__ out,
    int E)
{
    __shared__ float w2s[HDIM];
    const int tid = threadIdx.x;
    if (tid < HDIM) w2s[tid] = W2[tid];
    __syncthreads();

    const int warp = tid >> 5;
    const int lane = tid & 31;
    const int e = blockIdx.x * 8 + warp;
    if (e >= E) return;

    const int r = ei[e];
    const int c = ei[(size_t)E + e];

    const float4* __restrict__ pa = (const float4*)(g_AB + (size_t)r * NCOLS);
    const float4* __restrict__ pb = (const float4*)(g_AB + (size_t)c * NCOLS + HDIM);
    const float4* __restrict__ pw = (const float4*)w2s;

    float sum = 0.f;
    #pragma unroll
    for (int i = 0; i < 2; ++i) {
        const int idx = lane + i * 32;    // float4 index 0..63 covers 256 floats
        float4 a = pa[idx];
        float4 b = pb[idx];
        float4 w = pw[idx];
        float h0 = fmaxf(a.x + b.x, 0.f);
        float h1 = fmaxf(a.y + b.y, 0.f);
        float h2 = fmaxf(a.z + b.z, 0.f);
        float h3 = fmaxf(a.w + b.w, 0.f);
        sum = fmaf(h0, w.x, sum);
        sum = fmaf(h1, w.y, sum);
        sum = fmaf(h2, w.z, sum);
        sum = fmaf(h3, w.w, sum);
    }

    #pragma unroll
    for (int off = 16; off; off >>= 1)
        sum += __shfl_xor_sync(0xffffffff, sum, off);

    if (lane == 0) {
        const float z = sum + b2[0];      // TEMPERATURE = 1.0
        out[e] = 1.f / (1.f + expf(-z));
    }
}

// ----------------------------------------------------------------------------
// Launch
// ----------------------------------------------------------------------------
extern "C" void kernel_launch(void* const* d_in, const int* in_sizes, int n_in,
                              void* d_out, int out_size)
{
    const float* x   = (const float*)d_in[0];
    const int*   ei  = (const int*)d_in[1];
    const float* W1  = (const float*)d_in[2];
    const float* b1  = (const float*)d_in[3];
    const float* W2  = (const float*)d_in[4];
    const float* b2  = (const float*)d_in[5];
    float*       out = (float*)d_out;

    const int Nn = in_sizes[0] / FDIM;       // 10000
    const int E  = in_sizes[1] / 2;          // 320000

    dim3 gblk(256);
    dim3 ggrid(NCOLS / BN, (Nn + BM - 1) / BM);
    node_gemm<<<ggrid, gblk>>>(x, W1, b1, Nn);

    const int eblocks = (E + 7) / 8;
    edge_kernel<<<eblocks, 256>>>(ei, W2, b2, out, E);
}

// round 6
// speedup vs baseline: 1.1411x; 1.1411x over previous
#include <cuda_runtime.h>
#include <math.h>
#include <stdint.h>

#define FDIM 256
#define HDIM 256
#define NCOLS 512          // [A(256) | B(256)] per node
#define MAXN 10000

__device__ float g_AB[(size_t)MAXN * NCOLS];

// ----------------------------------------------------------------------------
// tf32 mma.sync helpers
// ----------------------------------------------------------------------------
__device__ __forceinline__ uint32_t f32_to_tf32(float x) {
    uint32_t r;
    asm("cvt.rna.tf32.f32 %0, %1;" : "=r"(r) : "f"(x));
    return r;
}

__device__ __forceinline__ void mma_tf32(float* d, const uint32_t* a, const uint32_t* b) {
    asm volatile(
        "mma.sync.aligned.m16n8k8.row.col.f32.tf32.tf32.f32 "
        "{%0,%1,%2,%3}, {%4,%5,%6,%7}, {%8,%9}, {%0,%1,%2,%3};\n"
        : "+f"(d[0]), "+f"(d[1]), "+f"(d[2]), "+f"(d[3])
        : "r"(a[0]), "r"(a[1]), "r"(a[2]), "r"(a[3]), "r"(b[0]), "r"(b[1]));
}

// ----------------------------------------------------------------------------
// Kernel 1: node projection GEMM, tf32 tensor cores.
// C[n][j] = sum_k X[n][k] * Wrow_j[k] + bias(j)
//   j <  256: Wrow_j = W1[j][0:256],        bias = b1[j]
//   j >= 256: Wrow_j = W1[j-256][256:512],  bias = 0
// Block tile 128x64x16, 8 warps (warp tile 32x32), double-buffered smem.
// smem layout [m][k] with row stride KPAD=20 -> conflict-free fragment loads.
// ----------------------------------------------------------------------------
#define GBM 128
#define GBN 64
#define GBK 16
#define KPAD 20

__global__ __launch_bounds__(256, 2) void node_gemm(
    const float* __restrict__ X,
    const float* __restrict__ W1,
    const float* __restrict__ b1,
    int nrows)
{
    __shared__ float As[2][GBM][KPAD];   // 20480 B
    __shared__ float Bs[2][GBN][KPAD];   // 10240 B

    const int tid  = threadIdx.x;
    const int lane = tid & 31;
    const int warp = tid >> 5;
    const int g    = lane >> 2;      // 0..7
    const int tig  = lane & 3;       // 0..3
    const int wm   = (warp & 3) * 32;    // warp M offset in block
    const int wn   = (warp >> 2) * 32;   // warp N offset in block

    const int m0 = blockIdx.y * GBM;
    const int n0 = blockIdx.x * GBN;

    // gmem load mapping
    const int xr = tid >> 2;             // 0..63 (rows xr and xr+64)
    const int kq = (tid & 3) * 4;        // 0,4,8,12
    const int gm0 = m0 + xr;
    const int gm1 = m0 + xr + 64;
    const bool v0 = (gm0 < nrows);
    const bool v1 = (gm1 < nrows);
    const float* xp0 = X + (size_t)(v0 ? gm0 : 0) * FDIM + kq;
    const float* xp1 = X + (size_t)(v1 ? gm1 : 0) * FDIM + kq;

    const int j = n0 + xr;               // output column this thread loads W for
    const float* wp = ((j < HDIM) ? (W1 + (size_t)j * (2 * FDIM))
                                  : (W1 + (size_t)(j - HDIM) * (2 * FDIM) + FDIM)) + kq;

    // ---- preload tile 0 ----
    {
        float4 x0 = v0 ? *(const float4*)(xp0) : make_float4(0,0,0,0);
        float4 x1 = v1 ? *(const float4*)(xp1) : make_float4(0,0,0,0);
        float4 w  = *(const float4*)(wp);
        As[0][xr     ][kq+0] = __uint_as_float(f32_to_tf32(x0.x));
        As[0][xr     ][kq+1] = __uint_as_float(f32_to_tf32(x0.y));
        As[0][xr     ][kq+2] = __uint_as_float(f32_to_tf32(x0.z));
        As[0][xr     ][kq+3] = __uint_as_float(f32_to_tf32(x0.w));
        As[0][xr + 64][kq+0] = __uint_as_float(f32_to_tf32(x1.x));
        As[0][xr + 64][kq+1] = __uint_as_float(f32_to_tf32(x1.y));
        As[0][xr + 64][kq+2] = __uint_as_float(f32_to_tf32(x1.z));
        As[0][xr + 64][kq+3] = __uint_as_float(f32_to_tf32(x1.w));
        Bs[0][xr][kq+0] = __uint_as_float(f32_to_tf32(w.x));
        Bs[0][xr][kq+1] = __uint_as_float(f32_to_tf32(w.y));
        Bs[0][xr][kq+2] = __uint_as_float(f32_to_tf32(w.z));
        Bs[0][xr][kq+3] = __uint_as_float(f32_to_tf32(w.w));
    }
    __syncthreads();

    float acc[2][4][4];
    #pragma unroll
    for (int mi = 0; mi < 2; ++mi)
        #pragma unroll
        for (int ni = 0; ni < 4; ++ni)
            #pragma unroll
            for (int q = 0; q < 4; ++q) acc[mi][ni][q] = 0.f;

    const int NITER = FDIM / GBK;        // 16
    #pragma unroll 1
    for (int iter = 1; iter <= NITER; ++iter) {
        const int k0 = iter * GBK;
        const int buf = (iter - 1) & 1;

        // prefetch next tile into regs
        float4 x0, x1, w;
        if (iter < NITER) {
            x0 = v0 ? *(const float4*)(xp0 + k0) : make_float4(0,0,0,0);
            x1 = v1 ? *(const float4*)(xp1 + k0) : make_float4(0,0,0,0);
            w  = *(const float4*)(wp + k0);
        }

        // compute current buffer: 2 k-steps of 8
        #pragma unroll
        for (int ks = 0; ks < GBK; ks += 8) {
            uint32_t af[2][4], bf[4][2];
            #pragma unroll
            for (int mi = 0; mi < 2; ++mi) {
                const int rb = wm + mi * 16;
                af[mi][0] = __float_as_uint(As[buf][rb + g    ][ks + tig    ]);
                af[mi][1] = __float_as_uint(As[buf][rb + g + 8][ks + tig    ]);
                af[mi][2] = __float_as_uint(As[buf][rb + g    ][ks + tig + 4]);
                af[mi][3] = __float_as_uint(As[buf][rb + g + 8][ks + tig + 4]);
            }
            #pragma unroll
            for (int ni = 0; ni < 4; ++ni) {
                const int cb = wn + ni * 8;
                bf[ni][0] = __float_as_uint(Bs[buf][cb + g][ks + tig    ]);
                bf[ni][1] = __float_as_uint(Bs[buf][cb + g][ks + tig + 4]);
            }
            #pragma unroll
            for (int mi = 0; mi < 2; ++mi)
                #pragma unroll
                for (int ni = 0; ni < 4; ++ni)
                    mma_tf32(acc[mi][ni], af[mi], bf[ni]);
        }

        // store prefetched tile into other buffer
        if (iter < NITER) {
            const int nb = buf ^ 1;
            As[nb][xr     ][kq+0] = __uint_as_float(f32_to_tf32(x0.x));
            As[nb][xr     ][kq+1] = __uint_as_float(f32_to_tf32(x0.y));
            As[nb][xr     ][kq+2] = __uint_as_float(f32_to_tf32(x0.z));
            As[nb][xr     ][kq+3] = __uint_as_float(f32_to_tf32(x0.w));
            As[nb][xr + 64][kq+0] = __uint_as_float(f32_to_tf32(x1.x));
            As[nb][xr + 64][kq+1] = __uint_as_float(f32_to_tf32(x1.y));
            As[nb][xr + 64][kq+2] = __uint_as_float(f32_to_tf32(x1.z));
            As[nb][xr + 64][kq+3] = __uint_as_float(f32_to_tf32(x1.w));
            Bs[nb][xr][kq+0] = __uint_as_float(f32_to_tf32(w.x));
            Bs[nb][xr][kq+1] = __uint_as_float(f32_to_tf32(w.y));
            Bs[nb][xr][kq+2] = __uint_as_float(f32_to_tf32(w.z));
            Bs[nb][xr][kq+3] = __uint_as_float(f32_to_tf32(w.w));
            __syncthreads();
        }
    }

    // ---- epilogue: bias + store (float2 per c-pair) ----
    const bool isA = (n0 < HDIM);
    #pragma unroll
    for (int ni = 0; ni < 4; ++ni) {
        const int col = n0 + wn + ni * 8 + 2 * tig;
        const float bias0 = isA ? b1[col]     : 0.f;
        const float bias1 = isA ? b1[col + 1] : 0.f;
        #pragma unroll
        for (int mi = 0; mi < 2; ++mi) {
            const int rb = m0 + wm + mi * 16;
            const int r0 = rb + g;
            const int r1 = rb + g + 8;
            if (r0 < nrows) {
                float2 v = make_float2(acc[mi][ni][0] + bias0, acc[mi][ni][1] + bias1);
                *(float2*)(g_AB + (size_t)r0 * NCOLS + col) = v;
            }
            if (r1 < nrows) {
                float2 v = make_float2(acc[mi][ni][2] + bias0, acc[mi][ni][3] + bias1);
                *(float2*)(g_AB + (size_t)r1 * NCOLS + col) = v;
            }
        }
    }
}

// ----------------------------------------------------------------------------
// Kernel 2: persistent warp-per-edge, 2 edges per loop iteration.
//   h = relu(A[row] + B[col]);  out = sigmoid(h . W2 + b2)
// W2 held in registers (2 float4 per lane). 16 LDG.128 in flight per lane.
// ----------------------------------------------------------------------------
__global__ __launch_bounds__(256) void edge_kernel(
    const int* __restrict__ ei,
    const float* __restrict__ W2,
    const float* __restrict__ b2,
    float* __restrict__ out,
    int E)
{
    const int lane = threadIdx.x & 31;
    const int gw = (blockIdx.x * blockDim.x + threadIdx.x) >> 5;
    const int nw = (gridDim.x * blockDim.x) >> 5;

    const float4* __restrict__ pw = (const float4*)W2;
    const float4 w0 = __ldg(pw + lane);
    const float4 w1 = __ldg(pw + lane + 32);
    const float bb = __ldg(b2);

    for (int e0 = gw * 2; e0 < E; e0 += nw * 2) {
        const int e1 = e0 + 1;
        const bool has2 = (e1 < E);
        const int r0 = ei[e0];
        const int c0 = ei[(size_t)E + e0];
        const int r1 = has2 ? ei[e1] : r0;
        const int c1 = has2 ? ei[(size_t)E + e1] : c0;

        const float4* pa0 = (const float4*)(g_AB + (size_t)r0 * NCOLS);
        const float4* pb0 = (const float4*)(g_AB + (size_t)c0 * NCOLS + HDIM);
        const float4* pa1 = (const float4*)(g_AB + (size_t)r1 * NCOLS);
        const float4* pb1 = (const float4*)(g_AB + (size_t)c1 * NCOLS + HDIM);

        // issue all gathers up front (MLP = 16 per lane)
        const float4 a00 = pa0[lane], a01 = pa0[lane + 32];
        const float4 b00 = pb0[lane], b01 = pb0[lane + 32];
        const float4 a10 = pa1[lane], a11 = pa1[lane + 32];
        const float4 b10 = pb1[lane], b11 = pb1[lane + 32];

        float s0 = 0.f, s1 = 0.f;
        s0 = fmaf(fmaxf(a00.x + b00.x, 0.f), w0.x, s0);
        s0 = fmaf(fmaxf(a00.y + b00.y, 0.f), w0.y, s0);
        s0 = fmaf(fmaxf(a00.z + b00.z, 0.f), w0.z, s0);
        s0 = fmaf(fmaxf(a00.w + b00.w, 0.f), w0.w, s0);
        s0 = fmaf(fmaxf(a01.x + b01.x, 0.f), w1.x, s0);
        s0 = fmaf(fmaxf(a01.y + b01.y, 0.f), w1.y, s0);
        s0 = fmaf(fmaxf(a01.z + b01.z, 0.f), w1.z, s0);
        s0 = fmaf(fmaxf(a01.w + b01.w, 0.f), w1.w, s0);

        s1 = fmaf(fmaxf(a10.x + b10.x, 0.f), w0.x, s1);
        s1 = fmaf(fmaxf(a10.y + b10.y, 0.f), w0.y, s1);
        s1 = fmaf(fmaxf(a10.z + b10.z, 0.f), w0.z, s1);
        s1 = fmaf(fmaxf(a10.w + b10.w, 0.f), w0.w, s1);
        s1 = fmaf(fmaxf(a11.x + b11.x, 0.f), w1.x, s1);
        s1 = fmaf(fmaxf(a11.y + b11.y, 0.f), w1.y, s1);
        s1 = fmaf(fmaxf(a11.z + b11.z, 0.f), w1.z, s1);
        s1 = fmaf(fmaxf(a11.w + b11.w, 0.f), w1.w, s1);

        #pragma unroll
        for (int off = 16; off; off >>= 1) {
            s0 += __shfl_xor_sync(0xffffffff, s0, off);
            s1 += __shfl_xor_sync(0xffffffff, s1, off);
        }

        if (lane == 0) out[e0] = 1.f / (1.f + expf(-(s0 + bb)));
        if (lane == 1 && has2) out[e1] = 1.f / (1.f + expf(-(s1 + bb)));
    }
}

// ----------------------------------------------------------------------------
// Launch
// ----------------------------------------------------------------------------
extern "C" void kernel_launch(void* const* d_in, const int* in_sizes, int n_in,
                              void* d_out, int out_size)
{
    const float* x   = (const float*)d_in[0];
    const int*   ei  = (const int*)d_in[1];
    const float* W1  = (const float*)d_in[2];
    const float* b1  = (const float*)d_in[3];
    const float* W2  = (const float*)d_in[4];
    const float* b2  = (const float*)d_in[5];
    float*       out = (float*)d_out;

    const int Nn = in_sizes[0] / FDIM;       // 10000
    const int E  = in_sizes[1] / 2;          // 320000

    dim3 ggrid(NCOLS / GBN, (Nn + GBM - 1) / GBM);   // (8, 79)
    node_gemm<<<ggrid, 256>>>(x, W1, b1, Nn);

    edge_kernel<<<1184, 256>>>(ei, W2, b2, out, E);
}

// round 7
// speedup vs baseline: 1.7519x; 1.5352x over previous
#include <cuda_runtime.h>
#include <cuda_fp16.h>
#include <math.h>
#include <stdint.h>

#define FDIM 256
#define HDIM 256
#define NCOLS 512          // [A(256) | B(256)] per node
#define MAXN 10000

__device__ __half g_ABh[(size_t)MAXN * NCOLS];   // 10.24 MB, L2-resident

// ----------------------------------------------------------------------------
// tf32 mma.sync helpers
// ----------------------------------------------------------------------------
__device__ __forceinline__ uint32_t f32_to_tf32(float x) {
    uint32_t r;
    asm("cvt.rna.tf32.f32 %0, %1;" : "=r"(r) : "f"(x));
    return r;
}

__device__ __forceinline__ void mma_tf32(float* d, const uint32_t* a, const uint32_t* b) {
    asm volatile(
        "mma.sync.aligned.m16n8k8.row.col.f32.tf32.tf32.f32 "
        "{%0,%1,%2,%3}, {%4,%5,%6,%7}, {%8,%9}, {%0,%1,%2,%3};\n"
        : "+f"(d[0]), "+f"(d[1]), "+f"(d[2]), "+f"(d[3])
        : "r"(a[0]), "r"(a[1]), "r"(a[2]), "r"(a[3]), "r"(b[0]), "r"(b[1]));
}

// ----------------------------------------------------------------------------
// Kernel 1: node projection GEMM, tf32 tensor cores, fp16 output table.
// C[n][j] = sum_k X[n][k] * Wrow_j[k] + bias(j)
//   j <  256: Wrow_j = W1[j][0:256],        bias = b1[j]
//   j >= 256: Wrow_j = W1[j-256][256:512],  bias = 0
// Block tile 128x64x16, 8 warps (warp tile 32x32), double-buffered smem.
// ----------------------------------------------------------------------------
#define GBM 128
#define GBN 64
#define GBK 16
#define KPAD 20

__global__ __launch_bounds__(256, 2) void node_gemm(
    const float* __restrict__ X,
    const float* __restrict__ W1,
    const float* __restrict__ b1,
    int nrows)
{
    __shared__ float As[2][GBM][KPAD];
    __shared__ float Bs[2][GBN][KPAD];

    const int tid  = threadIdx.x;
    const int lane = tid & 31;
    const int warp = tid >> 5;
    const int g    = lane >> 2;          // 0..7
    const int tig  = lane & 3;           // 0..3
    const int wm   = (warp & 3) * 32;
    const int wn   = (warp >> 2) * 32;

    const int m0 = blockIdx.y * GBM;
    const int n0 = blockIdx.x * GBN;

    const int xr = tid >> 2;             // 0..63
    const int kq = (tid & 3) * 4;
    const int gm0 = m0 + xr;
    const int gm1 = m0 + xr + 64;
    const bool v0 = (gm0 < nrows);
    const bool v1 = (gm1 < nrows);
    const float* xp0 = X + (size_t)(v0 ? gm0 : 0) * FDIM + kq;
    const float* xp1 = X + (size_t)(v1 ? gm1 : 0) * FDIM + kq;

    const int j = n0 + xr;
    const float* wp = ((j < HDIM) ? (W1 + (size_t)j * (2 * FDIM))
                                  : (W1 + (size_t)(j - HDIM) * (2 * FDIM) + FDIM)) + kq;

    {
        float4 x0 = v0 ? *(const float4*)(xp0) : make_float4(0,0,0,0);
        float4 x1 = v1 ? *(const float4*)(xp1) : make_float4(0,0,0,0);
        float4 w  = *(const float4*)(wp);
        As[0][xr     ][kq+0] = __uint_as_float(f32_to_tf32(x0.x));
        As[0][xr     ][kq+1] = __uint_as_float(f32_to_tf32(x0.y));
        As[0][xr     ][kq+2] = __uint_as_float(f32_to_tf32(x0.z));
        As[0][xr     ][kq+3] = __uint_as_float(f32_to_tf32(x0.w));
        As[0][xr + 64][kq+0] = __uint_as_float(f32_to_tf32(x1.x));
        As[0][xr + 64][kq+1] = __uint_as_float(f32_to_tf32(x1.y));
        As[0][xr + 64][kq+2] = __uint_as_float(f32_to_tf32(x1.z));
        As[0][xr + 64][kq+3] = __uint_as_float(f32_to_tf32(x1.w));
        Bs[0][xr][kq+0] = __uint_as_float(f32_to_tf32(w.x));
        Bs[0][xr][kq+1] = __uint_as_float(f32_to_tf32(w.y));
        Bs[0][xr][kq+2] = __uint_as_float(f32_to_tf32(w.z));
        Bs[0][xr][kq+3] = __uint_as_float(f32_to_tf32(w.w));
    }
    __syncthreads();

    float acc[2][4][4];
    #pragma unroll
    for (int mi = 0; mi < 2; ++mi)
        #pragma unroll
        for (int ni = 0; ni < 4; ++ni)
            #pragma unroll
            for (int q = 0; q < 4; ++q) acc[mi][ni][q] = 0.f;

    const int NITER = FDIM / GBK;
    #pragma unroll 1
    for (int iter = 1; iter <= NITER; ++iter) {
        const int k0 = iter * GBK;
        const int buf = (iter - 1) & 1;

        float4 x0, x1, w;
        if (iter < NITER) {
            x0 = v0 ? *(const float4*)(xp0 + k0) : make_float4(0,0,0,0);
            x1 = v1 ? *(const float4*)(xp1 + k0) : make_float4(0,0,0,0);
            w  = *(const float4*)(wp + k0);
        }

        #pragma unroll
        for (int ks = 0; ks < GBK; ks += 8) {
            uint32_t af[2][4], bf[4][2];
            #pragma unroll
            for (int mi = 0; mi < 2; ++mi) {
                const int rb = wm + mi * 16;
                af[mi][0] = __float_as_uint(As[buf][rb + g    ][ks + tig    ]);
                af[mi][1] = __float_as_uint(As[buf][rb + g + 8][ks + tig    ]);
                af[mi][2] = __float_as_uint(As[buf][rb + g    ][ks + tig + 4]);
                af[mi][3] = __float_as_uint(As[buf][rb + g + 8][ks + tig + 4]);
            }
            #pragma unroll
            for (int ni = 0; ni < 4; ++ni) {
                const int cb = wn + ni * 8;
                bf[ni][0] = __float_as_uint(Bs[buf][cb + g][ks + tig    ]);
                bf[ni][1] = __float_as_uint(Bs[buf][cb + g][ks + tig + 4]);
            }
            #pragma unroll
            for (int mi = 0; mi < 2; ++mi)
                #pragma unroll
                for (int ni = 0; ni < 4; ++ni)
                    mma_tf32(acc[mi][ni], af[mi], bf[ni]);
        }

        if (iter < NITER) {
            const int nb = buf ^ 1;
            As[nb][xr     ][kq+0] = __uint_as_float(f32_to_tf32(x0.x));
            As[nb][xr     ][kq+1] = __uint_as_float(f32_to_tf32(x0.y));
            As[nb][xr     ][kq+2] = __uint_as_float(f32_to_tf32(x0.z));
            As[nb][xr     ][kq+3] = __uint_as_float(f32_to_tf32(x0.w));
            As[nb][xr + 64][kq+0] = __uint_as_float(f32_to_tf32(x1.x));
            As[nb][xr + 64][kq+1] = __uint_as_float(f32_to_tf32(x1.y));
            As[nb][xr + 64][kq+2] = __uint_as_float(f32_to_tf32(x1.z));
            As[nb][xr + 64][kq+3] = __uint_as_float(f32_to_tf32(x1.w));
            Bs[nb][xr][kq+0] = __uint_as_float(f32_to_tf32(w.x));
            Bs[nb][xr][kq+1] = __uint_as_float(f32_to_tf32(w.y));
            Bs[nb][xr][kq+2] = __uint_as_float(f32_to_tf32(w.z));
            Bs[nb][xr][kq+3] = __uint_as_float(f32_to_tf32(w.w));
            __syncthreads();
        }
    }

    // ---- epilogue: bias + convert to fp16, store half2 ----
    const bool isA = (n0 < HDIM);
    #pragma unroll
    for (int ni = 0; ni < 4; ++ni) {
        const int col = n0 + wn + ni * 8 + 2 * tig;
        const float bias0 = isA ? b1[col]     : 0.f;
        const float bias1 = isA ? b1[col + 1] : 0.f;
        #pragma unroll
        for (int mi = 0; mi < 2; ++mi) {
            const int rb = m0 + wm + mi * 16;
            const int r0 = rb + g;
            const int r1 = rb + g + 8;
            if (r0 < nrows)
                *(__half2*)(g_ABh + (size_t)r0 * NCOLS + col) =
                    __floats2half2_rn(acc[mi][ni][0] + bias0, acc[mi][ni][1] + bias1);
            if (r1 < nrows)
                *(__half2*)(g_ABh + (size_t)r1 * NCOLS + col) =
                    __floats2half2_rn(acc[mi][ni][2] + bias0, acc[mi][ni][3] + bias1);
        }
    }
}

// ----------------------------------------------------------------------------
// Kernel 2: warp-per-edge, fp16 table. One LDG.128 per lane per side.
//   h = relu(A[row] + B[col]);  out = sigmoid(h . W2 + b2)
// ----------------------------------------------------------------------------
__global__ __launch_bounds__(256) void edge_kernel(
    const int* __restrict__ ei,
    const float* __restrict__ W2,
    const float* __restrict__ b2,
    float* __restrict__ out,
    int E)
{
    const int tid  = threadIdx.x;
    const int lane = tid & 31;
    const int warp = tid >> 5;
    const int e = blockIdx.x * 8 + warp;
    if (e >= E) return;

    const int r = ei[e];
    const int c = ei[(size_t)E + e];

    // W2: 8 consecutive floats per lane (cols lane*8 .. lane*8+7)
    const float4 wlo = __ldg((const float4*)W2 + lane * 2);
    const float4 whi = __ldg((const float4*)W2 + lane * 2 + 1);

    const uint4* __restrict__ pa = (const uint4*)(g_ABh + (size_t)r * NCOLS);
    const uint4* __restrict__ pb = (const uint4*)(g_ABh + (size_t)c * NCOLS + HDIM);
    const uint4 av = pa[lane];   // 8 halves
    const uint4 bv = pb[lane];

    const __half2* a2 = (const __half2*)&av;
    const __half2* b2h = (const __half2*)&bv;
    const __half2 zero = __half2half2(__float2half(0.f));

    float s = 0.f;
    {
        float2 h0 = __half22float2(__hmax2(__hadd2(a2[0], b2h[0]), zero));
        float2 h1 = __half22float2(__hmax2(__hadd2(a2[1], b2h[1]), zero));
        float2 h2 = __half22float2(__hmax2(__hadd2(a2[2], b2h[2]), zero));
        float2 h3 = __half22float2(__hmax2(__hadd2(a2[3], b2h[3]), zero));
        s = fmaf(h0.x, wlo.x, s);
        s = fmaf(h0.y, wlo.y, s);
        s = fmaf(h1.x, wlo.z, s);
        s = fmaf(h1.y, wlo.w, s);
        s = fmaf(h2.x, whi.x, s);
        s = fmaf(h2.y, whi.y, s);
        s = fmaf(h3.x, whi.z, s);
        s = fmaf(h3.y, whi.w, s);
    }

    #pragma unroll
    for (int off = 16; off; off >>= 1)
        s += __shfl_xor_sync(0xffffffff, s, off);

    if (lane == 0) {
        const float z = s + __ldg(b2);   // TEMPERATURE = 1.0
        out[e] = 1.f / (1.f + expf(-z));
    }
}

// ----------------------------------------------------------------------------
// Launch
// ----------------------------------------------------------------------------
extern "C" void kernel_launch(void* const* d_in, const int* in_sizes, int n_in,
                              void* d_out, int out_size)
{
    const float* x   = (const float*)d_in[0];
    const int*   ei  = (const int*)d_in[1];
    const float* W1  = (const float*)d_in[2];
    const float* b1  = (const float*)d_in[3];
    const float* W2  = (const float*)d_in[4];
    const float* b2  = (const float*)d_in[5];
    float*       out = (float*)d_out;

    const int Nn = in_sizes[0] / FDIM;       // 10000
    const int E  = in_sizes[1] / 2;          // 320000

    dim3 ggrid(NCOLS / GBN, (Nn + GBM - 1) / GBM);   // (8, 79)
    node_gemm<<<ggrid, 256>>>(x, W1, b1, Nn);

    const int eblocks = (E + 7) / 8;                 // 40000
    edge_kernel<<<eblocks, 256>>>(ei, W2, b2, out, E);
}

// round 9
// speedup vs baseline: 2.0672x; 1.1800x over previous
#include <cuda_runtime.h>
#include <cuda_fp16.h>
#include <math.h>
#include <stdint.h>

#define FDIM 256
#define HDIM 256
#define NCOLS 512          // [A(256) | B(256)] per node
#define MAXN 10000

__device__ __half g_ABh[(size_t)MAXN * NCOLS];   // 10.24 MB, L2-resident

// ----------------------------------------------------------------------------
// tf32 mma.sync helpers
// ----------------------------------------------------------------------------
__device__ __forceinline__ uint32_t f32_to_tf32(float x) {
    uint32_t r;
    asm("cvt.rna.tf32.f32 %0, %1;" : "=r"(r) : "f"(x));
    return r;
}

__device__ __forceinline__ void mma_tf32(float* d, const uint32_t* a, const uint32_t* b) {
    asm volatile(
        "mma.sync.aligned.m16n8k8.row.col.f32.tf32.tf32.f32 "
        "{%0,%1,%2,%3}, {%4,%5,%6,%7}, {%8,%9}, {%0,%1,%2,%3};\n"
        : "+f"(d[0]), "+f"(d[1]), "+f"(d[2]), "+f"(d[3])
        : "r"(a[0]), "r"(a[1]), "r"(a[2]), "r"(a[3]), "r"(b[0]), "r"(b[1]));
}

// ----------------------------------------------------------------------------
// Kernel 1: node projection GEMM, tf32 tensor cores, fp16 output table.
// (unchanged from R7 — ~30 us)
// ----------------------------------------------------------------------------
#define GBM 128
#define GBN 64
#define GBK 16
#define KPAD 20

__global__ __launch_bounds__(256, 2) void node_gemm(
    const float* __restrict__ X,
    const float* __restrict__ W1,
    const float* __restrict__ b1,
    int nrows)
{
    __shared__ float As[2][GBM][KPAD];
    __shared__ float Bs[2][GBN][KPAD];

    const int tid  = threadIdx.x;
    const int lane = tid & 31;
    const int warp = tid >> 5;
    const int g    = lane >> 2;          // 0..7
    const int tig  = lane & 3;           // 0..3
    const int wm   = (warp & 3) * 32;
    const int wn   = (warp >> 2) * 32;

    const int m0 = blockIdx.y * GBM;
    const int n0 = blockIdx.x * GBN;

    const int xr = tid >> 2;             // 0..63
    const int kq = (tid & 3) * 4;
    const int gm0 = m0 + xr;
    const int gm1 = m0 + xr + 64;
    const bool v0 = (gm0 < nrows);
    const bool v1 = (gm1 < nrows);
    const float* xp0 = X + (size_t)(v0 ? gm0 : 0) * FDIM + kq;
    const float* xp1 = X + (size_t)(v1 ? gm1 : 0) * FDIM + kq;

    const int j = n0 + xr;
    const float* wp = ((j < HDIM) ? (W1 + (size_t)j * (2 * FDIM))
                                  : (W1 + (size_t)(j - HDIM) * (2 * FDIM) + FDIM)) + kq;

    {
        float4 x0 = v0 ? *(const float4*)(xp0) : make_float4(0,0,0,0);
        float4 x1 = v1 ? *(const float4*)(xp1) : make_float4(0,0,0,0);
        float4 w  = *(const float4*)(wp);
        As[0][xr     ][kq+0] = __uint_as_float(f32_to_tf32(x0.x));
        As[0][xr     ][kq+1] = __uint_as_float(f32_to_tf32(x0.y));
        As[0][xr     ][kq+2] = __uint_as_float(f32_to_tf32(x0.z));
        As[0][xr     ][kq+3] = __uint_as_float(f32_to_tf32(x0.w));
        As[0][xr + 64][kq+0] = __uint_as_float(f32_to_tf32(x1.x));
        As[0][xr + 64][kq+1] = __uint_as_float(f32_to_tf32(x1.y));
        As[0][xr + 64][kq+2] = __uint_as_float(f32_to_tf32(x1.z));
        As[0][xr + 64][kq+3] = __uint_as_float(f32_to_tf32(x1.w));
        Bs[0][xr][kq+0] = __uint_as_float(f32_to_tf32(w.x));
        Bs[0][xr][kq+1] = __uint_as_float(f32_to_tf32(w.y));
        Bs[0][xr][kq+2] = __uint_as_float(f32_to_tf32(w.z));
        Bs[0][xr][kq+3] = __uint_as_float(f32_to_tf32(w.w));
    }
    __syncthreads();

    float acc[2][4][4];
    #pragma unroll
    for (int mi = 0; mi < 2; ++mi)
        #pragma unroll
        for (int ni = 0; ni < 4; ++ni)
            #pragma unroll
            for (int q = 0; q < 4; ++q) acc[mi][ni][q] = 0.f;

    const int NITER = FDIM / GBK;
    #pragma unroll 1
    for (int iter = 1; iter <= NITER; ++iter) {
        const int k0 = iter * GBK;
        const int buf = (iter - 1) & 1;

        float4 x0, x1, w;
        if (iter < NITER) {
            x0 = v0 ? *(const float4*)(xp0 + k0) : make_float4(0,0,0,0);
            x1 = v1 ? *(const float4*)(xp1 + k0) : make_float4(0,0,0,0);
            w  = *(const float4*)(wp + k0);
        }

        #pragma unroll
        for (int ks = 0; ks < GBK; ks += 8) {
            uint32_t af[2][4], bf[4][2];
            #pragma unroll
            for (int mi = 0; mi < 2; ++mi) {
                const int rb = wm + mi * 16;
                af[mi][0] = __float_as_uint(As[buf][rb + g    ][ks + tig    ]);
                af[mi][1] = __float_as_uint(As[buf][rb + g + 8][ks + tig    ]);
                af[mi][2] = __float_as_uint(As[buf][rb + g    ][ks + tig + 4]);
                af[mi][3] = __float_as_uint(As[buf][rb + g + 8][ks + tig + 4]);
            }
            #pragma unroll
            for (int ni = 0; ni < 4; ++ni) {
                const int cb = wn + ni * 8;
                bf[ni][0] = __float_as_uint(Bs[buf][cb + g][ks + tig    ]);
                bf[ni][1] = __float_as_uint(Bs[buf][cb + g][ks + tig + 4]);
            }
            #pragma unroll
            for (int mi = 0; mi < 2; ++mi)
                #pragma unroll
                for (int ni = 0; ni < 4; ++ni)
                    mma_tf32(acc[mi][ni], af[mi], bf[ni]);
        }

        if (iter < NITER) {
            const int nb = buf ^ 1;
            As[nb][xr     ][kq+0] = __uint_as_float(f32_to_tf32(x0.x));
            As[nb][xr     ][kq+1] = __uint_as_float(f32_to_tf32(x0.y));
            As[nb][xr     ][kq+2] = __uint_as_float(f32_to_tf32(x0.z));
            As[nb][xr     ][kq+3] = __uint_as_float(f32_to_tf32(x0.w));
            As[nb][xr + 64][kq+0] = __uint_as_float(f32_to_tf32(x1.x));
            As[nb][xr + 64][kq+1] = __uint_as_float(f32_to_tf32(x1.y));
            As[nb][xr + 64][kq+2] = __uint_as_float(f32_to_tf32(x1.z));
            As[nb][xr + 64][kq+3] = __uint_as_float(f32_to_tf32(x1.w));
            Bs[nb][xr][kq+0] = __uint_as_float(f32_to_tf32(w.x));
            Bs[nb][xr][kq+1] = __uint_as_float(f32_to_tf32(w.y));
            Bs[nb][xr][kq+2] = __uint_as_float(f32_to_tf32(w.z));
            Bs[nb][xr][kq+3] = __uint_as_float(f32_to_tf32(w.w));
            __syncthreads();
        }
    }

    const bool isA = (n0 < HDIM);
    #pragma unroll
    for (int ni = 0; ni < 4; ++ni) {
        const int col = n0 + wn + ni * 8 + 2 * tig;
        const float bias0 = isA ? b1[col]     : 0.f;
        const float bias1 = isA ? b1[col + 1] : 0.f;
        #pragma unroll
        for (int mi = 0; mi < 2; ++mi) {
            const int rb = m0 + wm + mi * 16;
            const int r0 = rb + g;
            const int r1 = rb + g + 8;
            if (r0 < nrows)
                *(__half2*)(g_ABh + (size_t)r0 * NCOLS + col) =
                    __floats2half2_rn(acc[mi][ni][0] + bias0, acc[mi][ni][1] + bias1);
            if (r1 < nrows)
                *(__half2*)(g_ABh + (size_t)r1 * NCOLS + col) =
                    __floats2half2_rn(acc[mi][ni][2] + bias0, acc[mi][ni][3] + bias1);
        }
    }
}

// ----------------------------------------------------------------------------
// Kernel 2: 8 edges per warp, W2 amortized in registers, 2-edge unroll (MLP=4).
//   h = relu(A[row] + B[col]);  out = sigmoid(h . W2 + b2)
// ----------------------------------------------------------------------------
__device__ __forceinline__ float edge_dot(uint4 av, uint4 bv,
                                          float4 wlo, float4 whi)
{
    const __half2* a2 = (const __half2*)&av;
    const __half2* b2 = (const __half2*)&bv;
    const __half2 zero = __half2half2(__float2half(0.f));
    float2 h0 = __half22float2(__hmax2(__hadd2(a2[0], b2[0]), zero));
    float2 h1 = __half22float2(__hmax2(__hadd2(a2[1], b2[1]), zero));
    float2 h2 = __half22float2(__hmax2(__hadd2(a2[2], b2[2]), zero));
    float2 h3 = __half22float2(__hmax2(__hadd2(a2[3], b2[3]), zero));
    float s = 0.f;
    s = fmaf(h0.x, wlo.x, s);
    s = fmaf(h0.y, wlo.y, s);
    s = fmaf(h1.x, wlo.z, s);
    s = fmaf(h1.y, wlo.w, s);
    s = fmaf(h2.x, whi.x, s);
    s = fmaf(h2.y, whi.y, s);
    s = fmaf(h3.x, whi.z, s);
    s = fmaf(h3.y, whi.w, s);
    return s;
}

#define EDGES_PER_WARP 8

__global__ __launch_bounds__(256) void edge_kernel(
    const int* __restrict__ ei,
    const float* __restrict__ W2,
    const float* __restrict__ b2,
    float* __restrict__ out,
    int E)
{
    const int tid  = threadIdx.x;
    const int lane = tid & 31;
    const int warp = tid >> 5;

    // W2 loaded ONCE per warp: 8 consecutive floats per lane
    const float4 wlo = __ldg((const float4*)W2 + lane * 2);
    const float4 whi = __ldg((const float4*)W2 + lane * 2 + 1);
    const float bb = __ldg(b2);

    const int base = (blockIdx.x * 8 + warp) * EDGES_PER_WARP;

    #pragma unroll
    for (int i = 0; i < EDGES_PER_WARP; i += 2) {
        const int e0 = base + i;
        const int e1 = e0 + 1;
        if (e0 >= E) return;
        const bool has1 = (e1 < E);

        const int r0 = ei[e0];
        const int c0 = ei[(size_t)E + e0];
        const int r1 = has1 ? ei[e1] : r0;
        const int c1 = has1 ? ei[(size_t)E + e1] : c0;

        // 4 independent LDG.128 in flight
        const uint4 a0 = ((const uint4*)(g_ABh + (size_t)r0 * NCOLS))[lane];
        const uint4 b0 = ((const uint4*)(g_ABh + (size_t)c0 * NCOLS + HDIM))[lane];
        const uint4 a1 = ((const uint4*)(g_ABh + (size_t)r1 * NCOLS))[lane];
        const uint4 b1v = ((const uint4*)(g_ABh + (size_t)c1 * NCOLS + HDIM))[lane];

        float s0 = edge_dot(a0, b0, wlo, whi);
        float s1 = edge_dot(a1, b1v, wlo, whi);

        #pragma unroll
        for (int off = 16; off; off >>= 1) {
            s0 += __shfl_xor_sync(0xffffffff, s0, off);
            s1 += __shfl_xor_sync(0xffffffff, s1, off);
        }

        if (lane == 0)          out[e0] = 1.f / (1.f + expf(-(s0 + bb)));
        if (lane == 1 && has1)  out[e1] = 1.f / (1.f + expf(-(s1 + bb)));
    }
}

// ----------------------------------------------------------------------------
// Launch
// ----------------------------------------------------------------------------
extern "C" void kernel_launch(void* const* d_in, const int* in_sizes, int n_in,
                              void* d_out, int out_size)
{
    const float* x   = (const float*)d_in[0];
    const int*   ei  = (const int*)d_in[1];
    const float* W1  = (const float*)d_in[2];
    const float* b1  = (const float*)d_in[3];
    const float* W2  = (const float*)d_in[4];
    const float* b2  = (const float*)d_in[5];
    float*       out = (float*)d_out;

    const int Nn = in_sizes[0] / FDIM;       // 10000
    const int E  = in_sizes[1] / 2;          // 320000

    dim3 ggrid(NCOLS / GBN, (Nn + GBM - 1) / GBM);   // (8, 79)
    node_gemm<<<ggrid, 256>>>(x, W1, b1, Nn);

    const int edges_per_block = 8 * EDGES_PER_WARP;  // 64
    const int eblocks = (E + edges_per_block - 1) / edges_per_block;  // 5000
    edge_kernel<<<eblocks, 256>>>(ei, W2, b2, out, E);
}

// round 10
// speedup vs baseline: 2.3511x; 1.1374x over previous
#include <cuda_runtime.h>
#include <cuda_fp16.h>
#include <math.h>
#include <stdint.h>

#define FDIM 256
#define HDIM 256
#define NCOLS 512          // [A(256) | B(256)] per node
#define MAXN 10000

__device__ __half g_ABh[(size_t)MAXN * NCOLS];   // 10.24 MB, L2-resident

// ----------------------------------------------------------------------------
// fp16 mma.sync m16n8k16
// ----------------------------------------------------------------------------
__device__ __forceinline__ void mma_f16(float* d, const uint32_t* a, const uint32_t* b) {
    asm volatile(
        "mma.sync.aligned.m16n8k16.row.col.f32.f16.f16.f32 "
        "{%0,%1,%2,%3}, {%4,%5,%6,%7}, {%8,%9}, {%0,%1,%2,%3};\n"
        : "+f"(d[0]), "+f"(d[1]), "+f"(d[2]), "+f"(d[3])
        : "r"(a[0]), "r"(a[1]), "r"(a[2]), "r"(a[3]), "r"(b[0]), "r"(b[1]));
}

// ----------------------------------------------------------------------------
// Kernel 1: node projection GEMM, fp16 tensor cores (m16n8k16), fp16 table out.
// C[n][j] = sum_k X[n][k] * Wrow_j[k] + bias(j)
// Block tile 128x64x16, 8 warps (warp tile 32x32), double-buffered fp16 smem.
// Row stride 24 halves (48B) -> conflict-free half2 fragment loads.
// ----------------------------------------------------------------------------
#define GBM 128
#define GBN 64
#define GBK 16
#define KPH 24            // padded row stride in halves

__global__ __launch_bounds__(256, 2) void node_gemm(
    const float* __restrict__ X,
    const float* __restrict__ W1,
    const float* __restrict__ b1,
    int nrows)
{
    __shared__ __half As[2][GBM][KPH];   // 12288 B
    __shared__ __half Bs[2][GBN][KPH];   //  6144 B

    const int tid  = threadIdx.x;
    const int lane = tid & 31;
    const int warp = tid >> 5;
    const int g    = lane >> 2;          // 0..7
    const int tig  = lane & 3;           // 0..3
    const int wm   = (warp & 3) * 32;
    const int wn   = (warp >> 2) * 32;

    const int m0 = blockIdx.y * GBM;
    const int n0 = blockIdx.x * GBN;

    const int xr = tid >> 2;             // 0..63
    const int kq = (tid & 3) * 4;        // 0,4,8,12
    const int gm0 = m0 + xr;
    const int gm1 = m0 + xr + 64;
    const bool v0 = (gm0 < nrows);
    const bool v1 = (gm1 < nrows);
    const float* xp0 = X + (size_t)(v0 ? gm0 : 0) * FDIM + kq;
    const float* xp1 = X + (size_t)(v1 ? gm1 : 0) * FDIM + kq;

    const int j = n0 + xr;
    const float* wp = ((j < HDIM) ? (W1 + (size_t)j * (2 * FDIM))
                                  : (W1 + (size_t)(j - HDIM) * (2 * FDIM) + FDIM)) + kq;

    // pack float4 -> 4 halves (8B) store
    auto st4h = [](__half* dst, float4 v) {
        __half2 h01 = __floats2half2_rn(v.x, v.y);
        __half2 h23 = __floats2half2_rn(v.z, v.w);
        uint2 u;
        u.x = *(uint32_t*)&h01;
        u.y = *(uint32_t*)&h23;
        *(uint2*)dst = u;
    };

    // ---- preload tile 0 ----
    {
        float4 x0 = v0 ? *(const float4*)(xp0) : make_float4(0,0,0,0);
        float4 x1 = v1 ? *(const float4*)(xp1) : make_float4(0,0,0,0);
        float4 w  = *(const float4*)(wp);
        st4h(&As[0][xr     ][kq], x0);
        st4h(&As[0][xr + 64][kq], x1);
        st4h(&Bs[0][xr][kq], w);
    }
    __syncthreads();

    float acc[2][4][4];
    #pragma unroll
    for (int mi = 0; mi < 2; ++mi)
        #pragma unroll
        for (int ni = 0; ni < 4; ++ni)
            #pragma unroll
            for (int q = 0; q < 4; ++q) acc[mi][ni][q] = 0.f;

    const int NITER = FDIM / GBK;        // 16
    #pragma unroll 1
    for (int iter = 1; iter <= NITER; ++iter) {
        const int k0 = iter * GBK;
        const int buf = (iter - 1) & 1;

        float4 x0, x1, w;
        if (iter < NITER) {
            x0 = v0 ? *(const float4*)(xp0 + k0) : make_float4(0,0,0,0);
            x1 = v1 ? *(const float4*)(xp1 + k0) : make_float4(0,0,0,0);
            w  = *(const float4*)(wp + k0);
        }

        // one m16n8k16 k-step covers the whole GBK=16 tile
        {
            uint32_t af[2][4], bf[4][2];
            const int kc = 2 * tig;          // half-pair column
            #pragma unroll
            for (int mi = 0; mi < 2; ++mi) {
                const int rb = wm + mi * 16;
                af[mi][0] = *(const uint32_t*)&As[buf][rb + g    ][kc    ];
                af[mi][1] = *(const uint32_t*)&As[buf][rb + g + 8][kc    ];
                af[mi][2] = *(const uint32_t*)&As[buf][rb + g    ][kc + 8];
                af[mi][3] = *(const uint32_t*)&As[buf][rb + g + 8][kc + 8];
            }
            #pragma unroll
            for (int ni = 0; ni < 4; ++ni) {
                const int cb = wn + ni * 8;
                bf[ni][0] = *(const uint32_t*)&Bs[buf][cb + g][kc    ];
                bf[ni][1] = *(const uint32_t*)&Bs[buf][cb + g][kc + 8];
            }
            #pragma unroll
            for (int mi = 0; mi < 2; ++mi)
                #pragma unroll
                for (int ni = 0; ni < 4; ++ni)
                    mma_f16(acc[mi][ni], af[mi], bf[ni]);
        }

        if (iter < NITER) {
            const int nb = buf ^ 1;
            st4h(&As[nb][xr     ][kq], x0);
            st4h(&As[nb][xr + 64][kq], x1);
            st4h(&Bs[nb][xr][kq], w);
            __syncthreads();
        }
    }

    // ---- epilogue: bias + convert to fp16, store half2 ----
    const bool isA = (n0 < HDIM);
    #pragma unroll
    for (int ni = 0; ni < 4; ++ni) {
        const int col = n0 + wn + ni * 8 + 2 * tig;
        const float bias0 = isA ? b1[col]     : 0.f;
        const float bias1 = isA ? b1[col + 1] : 0.f;
        #pragma unroll
        for (int mi = 0; mi < 2; ++mi) {
            const int rb = m0 + wm + mi * 16;
            const int r0 = rb + g;
            const int r1 = rb + g + 8;
            if (r0 < nrows)
                *(__half2*)(g_ABh + (size_t)r0 * NCOLS + col) =
                    __floats2half2_rn(acc[mi][ni][0] + bias0, acc[mi][ni][1] + bias1);
            if (r1 < nrows)
                *(__half2*)(g_ABh + (size_t)r1 * NCOLS + col) =
                    __floats2half2_rn(acc[mi][ni][2] + bias0, acc[mi][ni][3] + bias1);
        }
    }
}

// ----------------------------------------------------------------------------
// Kernel 2: 8 edges per warp, W2 in registers, 4-edge unroll (MLP=8).
//   h = relu(A[row] + B[col]);  out = sigmoid(h . W2 + b2)
// ----------------------------------------------------------------------------
__device__ __forceinline__ float edge_dot(uint4 av, uint4 bv,
                                          float4 wlo, float4 whi)
{
    const __half2* a2 = (const __half2*)&av;
    const __half2* b2 = (const __half2*)&bv;
    const __half2 zero = __half2half2(__float2half(0.f));
    float2 h0 = __half22float2(__hmax2(__hadd2(a2[0], b2[0]), zero));
    float2 h1 = __half22float2(__hmax2(__hadd2(a2[1], b2[1]), zero));
    float2 h2 = __half22float2(__hmax2(__hadd2(a2[2], b2[2]), zero));
    float2 h3 = __half22float2(__hmax2(__hadd2(a2[3], b2[3]), zero));
    float s = 0.f;
    s = fmaf(h0.x, wlo.x, s);
    s = fmaf(h0.y, wlo.y, s);
    s = fmaf(h1.x, wlo.z, s);
    s = fmaf(h1.y, wlo.w, s);
    s = fmaf(h2.x, whi.x, s);
    s = fmaf(h2.y, whi.y, s);
    s = fmaf(h3.x, whi.z, s);
    s = fmaf(h3.y, whi.w, s);
    return s;
}

#define EDGES_PER_WARP 8

__global__ __launch_bounds__(256) void edge_kernel(
    const int* __restrict__ ei,
    const float* __restrict__ W2,
    const float* __restrict__ b2,
    float* __restrict__ out,
    int E)
{
    const int tid  = threadIdx.x;
    const int lane = tid & 31;
    const int warp = tid >> 5;

    // W2 loaded once per warp: 8 consecutive floats per lane
    const float4 wlo = __ldg((const float4*)W2 + lane * 2);
    const float4 whi = __ldg((const float4*)W2 + lane * 2 + 1);
    const float bb = __ldg(b2);

    const int base = (blockIdx.x * 8 + warp) * EDGES_PER_WARP;

    #pragma unroll
    for (int i = 0; i < EDGES_PER_WARP; i += 4) {
        const int e0 = base + i;
        if (e0 >= E) return;
        const bool has1 = (e0 + 1 < E);
        const bool has2 = (e0 + 2 < E);
        const bool has3 = (e0 + 3 < E);

        const int r0 = ei[e0];
        const int c0 = ei[(size_t)E + e0];
        const int r1 = has1 ? ei[e0 + 1] : r0;
        const int c1 = has1 ? ei[(size_t)E + e0 + 1] : c0;
        const int r2 = has2 ? ei[e0 + 2] : r0;
        const int c2 = has2 ? ei[(size_t)E + e0 + 2] : c0;
        const int r3 = has3 ? ei[e0 + 3] : r0;
        const int c3 = has3 ? ei[(size_t)E + e0 + 3] : c0;

        // 8 independent LDG.128 in flight
        const uint4 a0 = ((const uint4*)(g_ABh + (size_t)r0 * NCOLS))[lane];
        const uint4 b0 = ((const uint4*)(g_ABh + (size_t)c0 * NCOLS + HDIM))[lane];
        const uint4 a1 = ((const uint4*)(g_ABh + (size_t)r1 * NCOLS))[lane];
        const uint4 b1v = ((const uint4*)(g_ABh + (size_t)c1 * NCOLS + HDIM))[lane];
        const uint4 a2 = ((const uint4*)(g_ABh + (size_t)r2 * NCOLS))[lane];
        const uint4 b2v = ((const uint4*)(g_ABh + (size_t)c2 * NCOLS + HDIM))[lane];
        const uint4 a3 = ((const uint4*)(g_ABh + (size_t)r3 * NCOLS))[lane];
        const uint4 b3v = ((const uint4*)(g_ABh + (size_t)c3 * NCOLS + HDIM))[lane];

        float s0 = edge_dot(a0, b0, wlo, whi);
        float s1 = edge_dot(a1, b1v, wlo, whi);
        float s2 = edge_dot(a2, b2v, wlo, whi);
        float s3 = edge_dot(a3, b3v, wlo, whi);

        #pragma unroll
        for (int off = 16; off; off >>= 1) {
            s0 += __shfl_xor_sync(0xffffffff, s0, off);
            s1 += __shfl_xor_sync(0xffffffff, s1, off);
            s2 += __shfl_xor_sync(0xffffffff, s2, off);
            s3 += __shfl_xor_sync(0xffffffff, s3, off);
        }

        if (lane == 0)         out[e0]     = 1.f / (1.f + expf(-(s0 + bb)));
        if (lane == 1 && has1) out[e0 + 1] = 1.f / (1.f + expf(-(s1 + bb)));
        if (lane == 2 && has2) out[e0 + 2] = 1.f / (1.f + expf(-(s2 + bb)));
        if (lane == 3 && has3) out[e0 + 3] = 1.f / (1.f + expf(-(s3 + bb)));
    }
}

// ----------------------------------------------------------------------------
// Launch
// ----------------------------------------------------------------------------
extern "C" void kernel_launch(void* const* d_in, const int* in_sizes, int n_in,
                              void* d_out, int out_size)
{
    const float* x   = (const float*)d_in[0];
    const int*   ei  = (const int*)d_in[1];
    const float* W1  = (const float*)d_in[2];
    const float* b1  = (const float*)d_in[3];
    const float* W2  = (const float*)d_in[4];
    const float* b2  = (const float*)d_in[5];
    float*       out = (float*)d_out;

    const int Nn = in_sizes[0] / FDIM;       // 10000
    const int E  = in_sizes[1] / 2;          // 320000

    dim3 ggrid(NCOLS / GBN, (Nn + GBM - 1) / GBM);   // (8, 79)
    node_gemm<<<ggrid, 256>>>(x, W1, b1, Nn);

    const int edges_per_block = 8 * EDGES_PER_WARP;  // 64
    const int eblocks = (E + edges_per_block - 1) / edges_per_block;  // 5000
    edge_kernel<<<eblocks, 256>>>(ei, W2, b2, out, E);
}

// round 13
// speedup vs baseline: 2.4980x; 1.0625x over previous
#include <cuda_runtime.h>
#include <cuda_fp16.h>
#include <math.h>
#include <stdint.h>

#define FDIM 256
#define HDIM 256
#define NCOLS 512          // [A(256) | B(256)] per node
#define MAXN 10000

__device__ __half g_ABh[(size_t)MAXN * NCOLS];    // 10.24 MB table (output of GEMM)
__device__ __half g_Xh[(size_t)MAXN * FDIM];      // 5.12 MB fp16 X
__device__ __half g_Wh[(size_t)NCOLS * FDIM];     // 256 KB fp16 W (pre-split [A|B], K-major)

// ----------------------------------------------------------------------------
// Kernel 0: convert X and W1 to fp16 (W1 re-laid out: row j<256 -> W1[j][0:256],
// row j>=256 -> W1[j-256][256:512]).
// ----------------------------------------------------------------------------
__global__ void convert_kernel(const float* __restrict__ X,
                               const float* __restrict__ W1,
                               int nX4)   // number of float4 in X
{
    const int nW4 = NCOLS * (FDIM / 4);   // 32768
    const int total = nX4 + nW4;
    for (int idx = blockIdx.x * blockDim.x + threadIdx.x; idx < total;
         idx += gridDim.x * blockDim.x) {
        float4 v;
        __half* dst;
        if (idx < nX4) {
            v = ((const float4*)X)[idx];
            dst = g_Xh + (size_t)idx * 4;
        } else {
            const int t = idx - nX4;
            const int j = t >> 6;              // 0..511
            const int kq = (t & 63) * 4;       // 0..252
            const float* src = (j < HDIM) ? (W1 + (size_t)j * (2 * FDIM) + kq)
                                          : (W1 + (size_t)(j - HDIM) * (2 * FDIM) + FDIM + kq);
            v = *(const float4*)src;
            dst = g_Wh + (size_t)j * FDIM + kq;
        }
        __half2 h01 = __floats2half2_rn(v.x, v.y);
        __half2 h23 = __floats2half2_rn(v.z, v.w);
        uint2 u;
        u.x = *(uint32_t*)&h01;
        u.y = *(uint32_t*)&h23;
        *(uint2*)dst = u;
    }
}

// ----------------------------------------------------------------------------
// fp16 mma.sync m16n8k16
// ----------------------------------------------------------------------------
__device__ __forceinline__ void mma_f16(float* d, const uint32_t* a, const uint32_t* b) {
    asm volatile(
        "mma.sync.aligned.m16n8k16.row.col.f32.f16.f16.f32 "
        "{%0,%1,%2,%3}, {%4,%5,%6,%7}, {%8,%9}, {%0,%1,%2,%3};\n"
        : "+f"(d[0]), "+f"(d[1]), "+f"(d[2]), "+f"(d[3])
        : "r"(a[0]), "r"(a[1]), "r"(a[2]), "r"(a[3]), "r"(b[0]), "r"(b[1]));
}

// ----------------------------------------------------------------------------
// Kernel 1: node projection GEMM, fp16 in / fp16 tensor cores / fp16 table out.
// Block tile 128x64x32, 8 warps (warp tile 32x32), double-buffered fp16 smem.
// Row stride 40 halves (80B) -> conflict-free fragment loads.
// ----------------------------------------------------------------------------
#define GBM 128
#define GBN 64
#define GBK 32
#define KPH 40            // padded row stride in halves

__global__ __launch_bounds__(256, 2) void node_gemm(
    const float* __restrict__ b1,
    int nrows)
{
    __shared__ __half As[2][GBM][KPH];   // 20480 B
    __shared__ __half Bs[2][GBN][KPH];   // 10240 B

    const int tid  = threadIdx.x;
    const int lane = tid & 31;
    const int warp = tid >> 5;
    const int g    = lane >> 2;          // 0..7
    const int tig  = lane & 3;           // 0..3
    const int wm   = (warp & 3) * 32;
    const int wn   = (warp >> 2) * 32;

    const int m0 = blockIdx.y * GBM;
    const int n0 = blockIdx.x * GBN;

    // gmem load mapping (fp16, uint4 = 8 halves)
    const int arow = tid >> 1;               // 0..127
    const int ah   = (tid & 1) * 16;         // 0 or 16
    const int brow = tid >> 2;               // 0..63
    const int bh   = (tid & 3) * 8;          // 0,8,16,24

    const int gma = m0 + arow;
    const bool va = (gma < nrows);
    const __half* xp = g_Xh + (size_t)(va ? gma : 0) * FDIM + ah;
    const __half* wp = g_Wh + (size_t)(n0 + brow) * FDIM + bh;

    // ---- preload tile 0 ----
    {
        uint4 z = make_uint4(0,0,0,0);
        uint4 xa0 = va ? *(const uint4*)(xp)     : z;
        uint4 xa1 = va ? *(const uint4*)(xp + 8) : z;
        uint4 wb  = *(const uint4*)(wp);
        *(uint4*)&As[0][arow][ah]     = xa0;
        *(uint4*)&As[0][arow][ah + 8] = xa1;
        *(uint4*)&Bs[0][brow][bh]     = wb;
    }
    __syncthreads();

    float acc[2][4][4];
    #pragma unroll
    for (int mi = 0; mi < 2; ++mi)
        #pragma unroll
        for (int ni = 0; ni < 4; ++ni)
            #pragma unroll
            for (int q = 0; q < 4; ++q) acc[mi][ni][q] = 0.f;

    const int NITER = FDIM / GBK;        // 8
    #pragma unroll 1
    for (int iter = 1; iter <= NITER; ++iter) {
        const int k0 = iter * GBK;
        const int buf = (iter - 1) & 1;

        uint4 xa0, xa1, wb;
        if (iter < NITER) {
            uint4 z = make_uint4(0,0,0,0);
            xa0 = va ? *(const uint4*)(xp + k0)     : z;
            xa1 = va ? *(const uint4*)(xp + k0 + 8) : z;
            wb  = *(const uint4*)(wp + k0);
        }

        // two m16n8k16 k-steps cover GBK=32
        #pragma unroll
        for (int ks = 0; ks < GBK; ks += 16) {
            uint32_t af[2][4], bf[4][2];
            const int kc = ks + 2 * tig;
            #pragma unroll
            for (int mi = 0; mi < 2; ++mi) {
                const int rb = wm + mi * 16;
                af[mi][0] = *(const uint32_t*)&As[buf][rb + g    ][kc    ];
                af[mi][1] = *(const uint32_t*)&As[buf][rb + g + 8][kc    ];
                af[mi][2] = *(const uint32_t*)&As[buf][rb + g    ][kc + 8];
                af[mi][3] = *(const uint32_t*)&As[buf][rb + g + 8][kc + 8];
            }
            #pragma unroll
            for (int ni = 0; ni < 4; ++ni) {
                const int cb = wn + ni * 8;
                bf[ni][0] = *(const uint32_t*)&Bs[buf][cb + g][kc    ];
                bf[ni][1] = *(const uint32_t*)&Bs[buf][cb + g][kc + 8];
            }
            #pragma unroll
            for (int mi = 0; mi < 2; ++mi)
                #pragma unroll
                for (int ni = 0; ni < 4; ++ni)
                    mma_f16(acc[mi][ni], af[mi], bf[ni]);
        }

        if (iter < NITER) {
            const int nb = buf ^ 1;
            *(uint4*)&As[nb][arow][ah]     = xa0;
            *(uint4*)&As[nb][arow][ah + 8] = xa1;
            *(uint4*)&Bs[nb][brow][bh]     = wb;
            __syncthreads();
        }
    }

    // ---- epilogue: bias + convert to fp16, store half2 ----
    const bool isA = (n0 < HDIM);
    #pragma unroll
    for (int ni = 0; ni < 4; ++ni) {
        const int col = n0 + wn + ni * 8 + 2 * tig;
        const float bias0 = isA ? b1[col]     : 0.f;
        const float bias1 = isA ? b1[col + 1] : 0.f;
        #pragma unroll
        for (int mi = 0; mi < 2; ++mi) {
            const int rb = m0 + wm + mi * 16;
            const int r0 = rb + g;
            const int r1 = rb + g + 8;
            if (r0 < nrows)
                *(__half2*)(g_ABh + (size_t)r0 * NCOLS + col) =
                    __floats2half2_rn(acc[mi][ni][0] + bias0, acc[mi][ni][1] + bias1);
            if (r1 < nrows)
                *(__half2*)(g_ABh + (size_t)r1 * NCOLS + col) =
                    __floats2half2_rn(acc[mi][ni][2] + bias0, acc[mi][ni][3] + bias1);
        }
    }
}

// ----------------------------------------------------------------------------
// Kernel 2: 8 edges per warp, W2 amortized in registers, 2-edge unroll.
// (exact R9 configuration — 31.3 us measured)
// ----------------------------------------------------------------------------
__device__ __forceinline__ float edge_dot(uint4 av, uint4 bv,
                                          float4 wlo, float4 whi)
{
    const __half2* a2 = (const __half2*)&av;
    const __half2* b2 = (const __half2*)&bv;
    const __half2 zero = __half2half2(__float2half(0.f));
    float2 h0 = __half22float2(__hmax2(__hadd2(a2[0], b2[0]), zero));
    float2 h1 = __half22float2(__hmax2(__hadd2(a2[1], b2[1]), zero));
    float2 h2 = __half22float2(__hmax2(__hadd2(a2[2], b2[2]), zero));
    float2 h3 = __half22float2(__hmax2(__hadd2(a2[3], b2[3]), zero));
    float s = 0.f;
    s = fmaf(h0.x, wlo.x, s);
    s = fmaf(h0.y, wlo.y, s);
    s = fmaf(h1.x, wlo.z, s);
    s = fmaf(h1.y, wlo.w, s);
    s = fmaf(h2.x, whi.x, s);
    s = fmaf(h2.y, whi.y, s);
    s = fmaf(h3.x, whi.z, s);
    s = fmaf(h3.y, whi.w, s);
    return s;
}

#define EDGES_PER_WARP 8

__global__ __launch_bounds__(256) void edge_kernel(
    const int* __restrict__ ei,
    const float* __restrict__ W2,
    const float* __restrict__ b2,
    float* __restrict__ out,
    int E)
{
    const int tid  = threadIdx.x;
    const int lane = tid & 31;
    const int warp = tid >> 5;

    const float4 wlo = __ldg((const float4*)W2 + lane * 2);
    const float4 whi = __ldg((const float4*)W2 + lane * 2 + 1);
    const float bb = __ldg(b2);

    const int base = (blockIdx.x * 8 + warp) * EDGES_PER_WARP;

    #pragma unroll
    for (int i = 0; i < EDGES_PER_WARP; i += 2) {
        const int e0 = base + i;
        const int e1 = e0 + 1;
        if (e0 >= E) return;
        const bool has1 = (e1 < E);

        const int r0 = ei[e0];
        const int c0 = ei[(size_t)E + e0];
        const int r1 = has1 ? ei[e1] : r0;
        const int c1 = has1 ? ei[(size_t)E + e1] : c0;

        const uint4 a0 = ((const uint4*)(g_ABh + (size_t)r0 * NCOLS))[lane];
        const uint4 b0 = ((const uint4*)(g_ABh + (size_t)c0 * NCOLS + HDIM))[lane];
        const uint4 a1 = ((const uint4*)(g_ABh + (size_t)r1 * NCOLS))[lane];
        const uint4 b1v = ((const uint4*)(g_ABh + (size_t)c1 * NCOLS + HDIM))[lane];

        float s0 = edge_dot(a0, b0, wlo, whi);
        float s1 = edge_dot(a1, b1v, wlo, whi);

        #pragma unroll
        for (int off = 16; off; off >>= 1) {
            s0 += __shfl_xor_sync(0xffffffff, s0, off);
            s1 += __shfl_xor_sync(0xffffffff, s1, off);
        }

        if (lane == 0)          out[e0] = 1.f / (1.f + expf(-(s0 + bb)));
        if (lane == 1 && has1)  out[e1] = 1.f / (1.f + expf(-(s1 + bb)));
    }
}

// ----------------------------------------------------------------------------
// Launch
// ----------------------------------------------------------------------------
extern "C" void kernel_launch(void* const* d_in, const int* in_sizes, int n_in,
                              void* d_out, int out_size)
{
    const float* x   = (const float*)d_in[0];
    const int*   ei  = (const int*)d_in[1];
    const float* W1  = (const float*)d_in[2];
    const float* b1  = (const float*)d_in[3];
    const float* W2  = (const float*)d_in[4];
    const float* b2  = (const float*)d_in[5];
    float*       out = (float*)d_out;

    const int Nn = in_sizes[0] / FDIM;       // 10000
    const int E  = in_sizes[1] / 2;          // 320000

    const int nX4 = Nn * (FDIM / 4);         // 640000
    const int nW4 = NCOLS * (FDIM / 4);      // 32768
    const int cblocks = (nX4 + nW4 + 4 * 256 - 1) / (4 * 256);  // ~657
    convert_kernel<<<cblocks, 256>>>(x, W1, nX4);

    dim3 ggrid(NCOLS / GBN, (Nn + GBM - 1) / GBM);   // (8, 79)
    node_gemm<<<ggrid, 256>>>(b1, Nn);

    const int edges_per_block = 8 * EDGES_PER_WARP;  // 64
    const int eblocks = (E + edges_per_block - 1) / edges_per_block;  // 5000
    edge_kernel<<<eblocks, 256>>>(ei, W2, b2, out, E);
}

// round 15
// speedup vs baseline: 2.5224x; 1.0097x over previous
#include <cuda_runtime.h>
#include <cuda_fp16.h>
#include <math.h>
#include <stdint.h>

#define FDIM 256
#define HDIM 256
#define NCOLS 512          // [A(256) | B(256)] per node
#define MAXN 10000

__device__ __half g_ABh[(size_t)MAXN * NCOLS];    // 10.24 MB table (output of GEMM)
__device__ __half g_Xh[(size_t)MAXN * FDIM];      // 5.12 MB fp16 X
__device__ __half g_Wh[(size_t)NCOLS * FDIM];     // 256 KB fp16 W (pre-split [A|B], K-major)

// ----------------------------------------------------------------------------
// Kernel 0: convert X and W1 to fp16. 4 independent float4 per thread (MLP=4).
// W1 re-laid out: row j<256 -> W1[j][0:256], row j>=256 -> W1[j-256][256:512].
// ----------------------------------------------------------------------------
__device__ __forceinline__ void cvt_store(int idx, const float* __restrict__ X,
                                          const float* __restrict__ W1, int nX4)
{
    float4 v;
    __half* dst;
    if (idx < nX4) {
        v = ((const float4*)X)[idx];
        dst = g_Xh + (size_t)idx * 4;
    } else {
        const int t = idx - nX4;
        const int j = t >> 6;              // 0..511
        const int kq = (t & 63) * 4;       // 0..252
        const float* src = (j < HDIM) ? (W1 + (size_t)j * (2 * FDIM) + kq)
                                      : (W1 + (size_t)(j - HDIM) * (2 * FDIM) + FDIM + kq);
        v = *(const float4*)src;
        dst = g_Wh + (size_t)j * FDIM + kq;
    }
    __half2 h01 = __floats2half2_rn(v.x, v.y);
    __half2 h23 = __floats2half2_rn(v.z, v.w);
    uint2 u;
    u.x = *(uint32_t*)&h01;
    u.y = *(uint32_t*)&h23;
    *(uint2*)dst = u;
}

__global__ void convert_kernel(const float* __restrict__ X,
                               const float* __restrict__ W1,
                               int nX4, int total)
{
    const int base = blockIdx.x * (blockDim.x * 4) + threadIdx.x;
    const int i0 = base;
    const int i1 = base + 256;
    const int i2 = base + 512;
    const int i3 = base + 768;
    // 4 independent load/convert/store chains
    if (i0 < total) cvt_store(i0, X, W1, nX4);
    if (i1 < total) cvt_store(i1, X, W1, nX4);
    if (i2 < total) cvt_store(i2, X, W1, nX4);
    if (i3 < total) cvt_store(i3, X, W1, nX4);
}

// ----------------------------------------------------------------------------
// fp16 mma.sync m16n8k16
// ----------------------------------------------------------------------------
__device__ __forceinline__ void mma_f16(float* d, const uint32_t* a, const uint32_t* b) {
    asm volatile(
        "mma.sync.aligned.m16n8k16.row.col.f32.f16.f16.f32 "
        "{%0,%1,%2,%3}, {%4,%5,%6,%7}, {%8,%9}, {%0,%1,%2,%3};\n"
        : "+f"(d[0]), "+f"(d[1]), "+f"(d[2]), "+f"(d[3])
        : "r"(a[0]), "r"(a[1]), "r"(a[2]), "r"(a[3]), "r"(b[0]), "r"(b[1]));
}

// ----------------------------------------------------------------------------
// Kernel 1: node projection GEMM, fp16 in / fp16 tensor cores / fp16 table out.
// Block tile 128x64x32, 8 warps (warp tile 32x32), double-buffered fp16 smem.
// Row stride 40 halves (80B) -> conflict-free fragment loads.
// min 3 blocks/SM for latency hiding (smem 30.7KB/block, 92KB of 228 used).
// ----------------------------------------------------------------------------
#define GBM 128
#define GBN 64
#define GBK 32
#define KPH 40            // padded row stride in halves

__global__ __launch_bounds__(256, 3) void node_gemm(
    const float* __restrict__ b1,
    int nrows)
{
    __shared__ __half As[2][GBM][KPH];   // 20480 B
    __shared__ __half Bs[2][GBN][KPH];   // 10240 B

    const int tid  = threadIdx.x;
    const int lane = tid & 31;
    const int warp = tid >> 5;
    const int g    = lane >> 2;          // 0..7
    const int tig  = lane & 3;           // 0..3
    const int wm   = (warp & 3) * 32;
    const int wn   = (warp >> 2) * 32;

    const int m0 = blockIdx.y * GBM;
    const int n0 = blockIdx.x * GBN;

    // gmem load mapping (fp16, uint4 = 8 halves)
    const int arow = tid >> 1;               // 0..127
    const int ah   = (tid & 1) * 16;         // 0 or 16
    const int brow = tid >> 2;               // 0..63
    const int bh   = (tid & 3) * 8;          // 0,8,16,24

    const int gma = m0 + arow;
    const bool va = (gma < nrows);
    const __half* xp = g_Xh + (size_t)(va ? gma : 0) * FDIM + ah;
    const __half* wp = g_Wh + (size_t)(n0 + brow) * FDIM + bh;

    // ---- preload tile 0 ----
    {
        uint4 z = make_uint4(0,0,0,0);
        uint4 xa0 = va ? *(const uint4*)(xp)     : z;
        uint4 xa1 = va ? *(const uint4*)(xp + 8) : z;
        uint4 wb  = *(const uint4*)(wp);
        *(uint4*)&As[0][arow][ah]     = xa0;
        *(uint4*)&As[0][arow][ah + 8] = xa1;
        *(uint4*)&Bs[0][brow][bh]     = wb;
    }
    __syncthreads();

    float acc[2][4][4];
    #pragma unroll
    for (int mi = 0; mi < 2; ++mi)
        #pragma unroll
        for (int ni = 0; ni < 4; ++ni)
            #pragma unroll
            for (int q = 0; q < 4; ++q) acc[mi][ni][q] = 0.f;

    const int NITER = FDIM / GBK;        // 8
    #pragma unroll 1
    for (int iter = 1; iter <= NITER; ++iter) {
        const int k0 = iter * GBK;
        const int buf = (iter - 1) & 1;

        uint4 xa0, xa1, wb;
        if (iter < NITER) {
            uint4 z = make_uint4(0,0,0,0);
            xa0 = va ? *(const uint4*)(xp + k0)     : z;
            xa1 = va ? *(const uint4*)(xp + k0 + 8) : z;
            wb  = *(const uint4*)(wp + k0);
        }

        // two m16n8k16 k-steps cover GBK=32
        #pragma unroll
        for (int ks = 0; ks < GBK; ks += 16) {
            uint32_t af[2][4], bf[4][2];
            const int kc = ks + 2 * tig;
            #pragma unroll
            for (int mi = 0; mi < 2; ++mi) {
                const int rb = wm + mi * 16;
                af[mi][0] = *(const uint32_t*)&As[buf][rb + g    ][kc    ];
                af[mi][1] = *(const uint32_t*)&As[buf][rb + g + 8][kc    ];
                af[mi][2] = *(const uint32_t*)&As[buf][rb + g    ][kc + 8];
                af[mi][3] = *(const uint32_t*)&As[buf][rb + g + 8][kc + 8];
            }
            #pragma unroll
            for (int ni = 0; ni < 4; ++ni) {
                const int cb = wn + ni * 8;
                bf[ni][0] = *(const uint32_t*)&Bs[buf][cb + g][kc    ];
                bf[ni][1] = *(const uint32_t*)&Bs[buf][cb + g][kc + 8];
            }
            #pragma unroll
            for (int mi = 0; mi < 2; ++mi)
                #pragma unroll
                for (int ni = 0; ni < 4; ++ni)
                    mma_f16(acc[mi][ni], af[mi], bf[ni]);
        }

        if (iter < NITER) {
            const int nb = buf ^ 1;
            *(uint4*)&As[nb][arow][ah]     = xa0;
            *(uint4*)&As[nb][arow][ah + 8] = xa1;
            *(uint4*)&Bs[nb][brow][bh]     = wb;
            __syncthreads();
        }
    }

    // ---- epilogue: bias + convert to fp16, store half2 ----
    const bool isA = (n0 < HDIM);
    #pragma unroll
    for (int ni = 0; ni < 4; ++ni) {
        const int col = n0 + wn + ni * 8 + 2 * tig;
        const float bias0 = isA ? b1[col]     : 0.f;
        const float bias1 = isA ? b1[col + 1] : 0.f;
        #pragma unroll
        for (int mi = 0; mi < 2; ++mi) {
            const int rb = m0 + wm + mi * 16;
            const int r0 = rb + g;
            const int r1 = rb + g + 8;
            if (r0 < nrows)
                *(__half2*)(g_ABh + (size_t)r0 * NCOLS + col) =
                    __floats2half2_rn(acc[mi][ni][0] + bias0, acc[mi][ni][1] + bias1);
            if (r1 < nrows)
                *(__half2*)(g_ABh + (size_t)r1 * NCOLS + col) =
                    __floats2half2_rn(acc[mi][ni][2] + bias0, acc[mi][ni][3] + bias1);
        }
    }
}

// ----------------------------------------------------------------------------
// Kernel 2: 8 edges per warp, W2 amortized in registers, 2-edge unroll.
// (exact R9 configuration — 31.3 us measured)
// ----------------------------------------------------------------------------
__device__ __forceinline__ float edge_dot(uint4 av, uint4 bv,
                                          float4 wlo, float4 whi)
{
    const __half2* a2 = (const __half2*)&av;
    const __half2* b2 = (const __half2*)&bv;
    const __half2 zero = __half2half2(__float2half(0.f));
    float2 h0 = __half22float2(__hmax2(__hadd2(a2[0], b2[0]), zero));
    float2 h1 = __half22float2(__hmax2(__hadd2(a2[1], b2[1]), zero));
    float2 h2 = __half22float2(__hmax2(__hadd2(a2[2], b2[2]), zero));
    float2 h3 = __half22float2(__hmax2(__hadd2(a2[3], b2[3]), zero));
    float s = 0.f;
    s = fmaf(h0.x, wlo.x, s);
    s = fmaf(h0.y, wlo.y, s);
    s = fmaf(h1.x, wlo.z, s);
    s = fmaf(h1.y, wlo.w, s);
    s = fmaf(h2.x, whi.x, s);
    s = fmaf(h2.y, whi.y, s);
    s = fmaf(h3.x, whi.z, s);
    s = fmaf(h3.y, whi.w, s);
    return s;
}

#define EDGES_PER_WARP 8

__global__ __launch_bounds__(256) void edge_kernel(
    const int* __restrict__ ei,
    const float* __restrict__ W2,
    const float* __restrict__ b2,
    float* __restrict__ out,
    int E)
{
    const int tid  = threadIdx.x;
    const int lane = tid & 31;
    const int warp = tid >> 5;

    const float4 wlo = __ldg((const float4*)W2 + lane * 2);
    const float4 whi = __ldg((const float4*)W2 + lane * 2 + 1);
    const float bb = __ldg(b2);

    const int base = (blockIdx.x * 8 + warp) * EDGES_PER_WARP;

    #pragma unroll
    for (int i = 0; i < EDGES_PER_WARP; i += 2) {
        const int e0 = base + i;
        const int e1 = e0 + 1;
        if (e0 >= E) return;
        const bool has1 = (e1 < E);

        const int r0 = ei[e0];
        const int c0 = ei[(size_t)E + e0];
        const int r1 = has1 ? ei[e1] : r0;
        const int c1 = has1 ? ei[(size_t)E + e1] : c0;

        const uint4 a0 = ((const uint4*)(g_ABh + (size_t)r0 * NCOLS))[lane];
        const uint4 b0 = ((const uint4*)(g_ABh + (size_t)c0 * NCOLS + HDIM))[lane];
        const uint4 a1 = ((const uint4*)(g_ABh + (size_t)r1 * NCOLS))[lane];
        const uint4 b1v = ((const uint4*)(g_ABh + (size_t)c1 * NCOLS + HDIM))[lane];

        float s0 = edge_dot(a0, b0, wlo, whi);
        float s1 = edge_dot(a1, b1v, wlo, whi);

        #pragma unroll
        for (int off = 16; off; off >>= 1) {
            s0 += __shfl_xor_sync(0xffffffff, s0, off);
            s1 += __shfl_xor_sync(0xffffffff, s1, off);
        }

        if (lane == 0)          out[e0] = 1.f / (1.f + expf(-(s0 + bb)));
        if (lane == 1 && has1)  out[e1] = 1.f / (1.f + expf(-(s1 + bb)));
    }
}

// ----------------------------------------------------------------------------
// Launch
// ----------------------------------------------------------------------------
extern "C" void kernel_launch(void* const* d_in, const int* in_sizes, int n_in,
                              void* d_out, int out_size)
{
    const float* x   = (const float*)d_in[0];
    const int*   ei  = (const int*)d_in[1];
    const float* W1  = (const float*)d_in[2];
    const float* b1  = (const float*)d_in[3];
    const float* W2  = (const float*)d_in[4];
    const float* b2  = (const float*)d_in[5];
    float*       out = (float*)d_out;

    const int Nn = in_sizes[0] / FDIM;       // 10000
    const int E  = in_sizes[1] / 2;          // 320000

    const int nX4 = Nn * (FDIM / 4);         // 640000
    const int nW4 = NCOLS * (FDIM / 4);      // 32768
    const int total = nX4 + nW4;             // 672768
    const int cblocks = (total + 1023) / 1024;  // 657
    convert_kernel<<<cblocks, 256>>>(x, W1, nX4, total);

    dim3 ggrid(NCOLS / GBN, (Nn + GBM - 1) / GBM);   // (8, 79)
    node_gemm<<<ggrid, 256>>>(b1, Nn);

    const int edges_per_block = 8 * EDGES_PER_WARP;  // 64
    const int eblocks = (E + edges_per_block - 1) / edges_per_block;  // 5000
    edge_kernel<<<eblocks, 256>>>(ei, W2, b2, out, E);
}

// round 16
// speedup vs baseline: 2.5938x; 1.0283x over previous
#include <cuda_runtime.h>
#include <cuda_fp16.h>
#include <math.h>
#include <stdint.h>

#define FDIM 256
#define HDIM 256
#define NCOLS 512          // [A(256) | B(256)] per node
#define MAXN 10000

__device__ __half g_ABh[(size_t)MAXN * NCOLS];    // 10.24 MB table (output of GEMM)
__device__ __half g_Xh[(size_t)MAXN * FDIM];      // 5.12 MB fp16 X
__device__ __half g_Wh[(size_t)NCOLS * FDIM];     // 256 KB fp16 W (pre-split [A|B], K-major)

// ----------------------------------------------------------------------------
// Kernel 0: convert X and W1 to fp16, guard-free 4-way MLP.
// Grid layout: blocks [0,625) cover X (625*1024 = 640000 float4 exactly),
//              blocks [625,657) cover W (32*1024 = 32768 float4 exactly).
// W1 re-laid out: row j<256 -> W1[j][0:256], row j>=256 -> W1[j-256][256:512].
// ----------------------------------------------------------------------------
__device__ __forceinline__ uint2 pack4h(float4 v) {
    __half2 h01 = __floats2half2_rn(v.x, v.y);
    __half2 h23 = __floats2half2_rn(v.z, v.w);
    uint2 u;
    u.x = *(uint32_t*)&h01;
    u.y = *(uint32_t*)&h23;
    return u;
}

__global__ void convert_kernel(const float* __restrict__ X,
                               const float* __restrict__ W1,
                               int bX)   // number of X blocks
{
    const int tid = threadIdx.x;
    if ((int)blockIdx.x < bX) {
        // ---- X region: 4 unconditional independent float4 loads ----
        const int base = blockIdx.x * 1024 + tid;
        const float4* src = (const float4*)X;
        float4 v0 = src[base];
        float4 v1 = src[base + 256];
        float4 v2 = src[base + 512];
        float4 v3 = src[base + 768];
        uint2* dst = (uint2*)g_Xh;
        dst[base]       = pack4h(v0);
        dst[base + 256] = pack4h(v1);
        dst[base + 512] = pack4h(v2);
        dst[base + 768] = pack4h(v3);
    } else {
        // ---- W region ----
        const int base = (blockIdx.x - bX) * 1024 + tid;
        float4 v[4];
        int t[4];
        #pragma unroll
        for (int q = 0; q < 4; ++q) {
            t[q] = base + q * 256;
            const int j  = t[q] >> 6;          // 0..511
            const int kq = (t[q] & 63) * 4;    // 0..252
            const float* src = (j < HDIM) ? (W1 + (size_t)j * (2 * FDIM) + kq)
                                          : (W1 + (size_t)(j - HDIM) * (2 * FDIM) + FDIM + kq);
            v[q] = *(const float4*)src;
        }
        uint2* dst = (uint2*)g_Wh;
        #pragma unroll
        for (int q = 0; q < 4; ++q)
            dst[t[q]] = pack4h(v[q]);
    }
}

// ----------------------------------------------------------------------------
// fp16 mma.sync m16n8k16
// ----------------------------------------------------------------------------
__device__ __forceinline__ void mma_f16(float* d, const uint32_t* a, const uint32_t* b) {
    asm volatile(
        "mma.sync.aligned.m16n8k16.row.col.f32.f16.f16.f32 "
        "{%0,%1,%2,%3}, {%4,%5,%6,%7}, {%8,%9}, {%0,%1,%2,%3};\n"
        : "+f"(d[0]), "+f"(d[1]), "+f"(d[2]), "+f"(d[3])
        : "r"(a[0]), "r"(a[1]), "r"(a[2]), "r"(a[3]), "r"(b[0]), "r"(b[1]));
}

// ----------------------------------------------------------------------------
// Kernel 1: node projection GEMM, fp16 TC, block tile 128x128x32.
// 8 warps, warp tile 32x64 (2x8 m16n8 tiles). Double-buffered smem, KPH=40.
// Grid (4, 79): X stripe re-reads cut from 8x to 4x.
// ----------------------------------------------------------------------------
#define GBM 128
#define GBN 128
#define GBK 32
#define KPH 40            // padded row stride in halves

__global__ __launch_bounds__(256, 2) void node_gemm(
    const float* __restrict__ b1,
    int nrows)
{
    __shared__ __half As[2][GBM][KPH];   // 20480 B
    __shared__ __half Bs[2][GBN][KPH];   // 20480 B

    const int tid  = threadIdx.x;
    const int lane = tid & 31;
    const int warp = tid >> 5;
    const int g    = lane >> 2;          // 0..7
    const int tig  = lane & 3;           // 0..3
    const int wm   = (warp & 3) * 32;    // warp M offset
    const int wn   = (warp >> 2) * 64;   // warp N offset

    const int m0 = blockIdx.x * GBM;
    const int n0 = blockIdx.y * GBN;

    // gmem load mapping (fp16, uint4 = 8 halves); both A and B: 128 rows
    const int arow = tid >> 1;               // 0..127
    const int ah   = (tid & 1) * 16;         // 0 or 16

    const int gma = m0 + arow;
    const bool va = (gma < nrows);
    const __half* xp = g_Xh + (size_t)(va ? gma : 0) * FDIM + ah;
    const __half* wp = g_Wh + (size_t)(n0 + arow) * FDIM + ah;

    // ---- preload tile 0 ----
    {
        uint4 z = make_uint4(0,0,0,0);
        uint4 xa0 = va ? *(const uint4*)(xp)     : z;
        uint4 xa1 = va ? *(const uint4*)(xp + 8) : z;
        uint4 wb0 = *(const uint4*)(wp);
        uint4 wb1 = *(const uint4*)(wp + 8);
        *(uint4*)&As[0][arow][ah]     = xa0;
        *(uint4*)&As[0][arow][ah + 8] = xa1;
        *(uint4*)&Bs[0][arow][ah]     = wb0;
        *(uint4*)&Bs[0][arow][ah + 8] = wb1;
    }
    __syncthreads();

    float acc[2][8][4];
    #pragma unroll
    for (int mi = 0; mi < 2; ++mi)
        #pragma unroll
        for (int ni = 0; ni < 8; ++ni)
            #pragma unroll
            for (int q = 0; q < 4; ++q) acc[mi][ni][q] = 0.f;

    const int NITER = FDIM / GBK;        // 8
    #pragma unroll 1
    for (int iter = 1; iter <= NITER; ++iter) {
        const int k0 = iter * GBK;
        const int buf = (iter - 1) & 1;

        uint4 xa0, xa1, wb0, wb1;
        if (iter < NITER) {
            uint4 z = make_uint4(0,0,0,0);
            xa0 = va ? *(const uint4*)(xp + k0)     : z;
            xa1 = va ? *(const uint4*)(xp + k0 + 8) : z;
            wb0 = *(const uint4*)(wp + k0);
            wb1 = *(const uint4*)(wp + k0 + 8);
        }

        // two m16n8k16 k-steps cover GBK=32
        #pragma unroll
        for (int ks = 0; ks < GBK; ks += 16) {
            uint32_t af[2][4], bf[8][2];
            const int kc = ks + 2 * tig;
            #pragma unroll
            for (int mi = 0; mi < 2; ++mi) {
                const int rb = wm + mi * 16;
                af[mi][0] = *(const uint32_t*)&As[buf][rb + g    ][kc    ];
                af[mi][1] = *(const uint32_t*)&As[buf][rb + g + 8][kc    ];
                af[mi][2] = *(const uint32_t*)&As[buf][rb + g    ][kc + 8];
                af[mi][3] = *(const uint32_t*)&As[buf][rb + g + 8][kc + 8];
            }
            #pragma unroll
            for (int ni = 0; ni < 8; ++ni) {
                const int cb = wn + ni * 8;
                bf[ni][0] = *(const uint32_t*)&Bs[buf][cb + g][kc    ];
                bf[ni][1] = *(const uint32_t*)&Bs[buf][cb + g][kc + 8];
            }
            #pragma unroll
            for (int mi = 0; mi < 2; ++mi)
                #pragma unroll
                for (int ni = 0; ni < 8; ++ni)
                    mma_f16(acc[mi][ni], af[mi], bf[ni]);
        }

        if (iter < NITER) {
            const int nb = buf ^ 1;
            *(uint4*)&As[nb][arow][ah]     = xa0;
            *(uint4*)&As[nb][arow][ah + 8] = xa1;
            *(uint4*)&Bs[nb][arow][ah]     = wb0;
            *(uint4*)&Bs[nb][arow][ah + 8] = wb1;
            __syncthreads();
        }
    }

    // ---- epilogue: bias + convert to fp16, store half2 ----
    const bool isA = (n0 < HDIM);   // GBN=128 <= HDIM, n0 multiple of 128
    #pragma unroll
    for (int ni = 0; ni < 8; ++ni) {
        const int col = n0 + wn + ni * 8 + 2 * tig;
        const float bias0 = isA ? b1[col]     : 0.f;
        const float bias1 = isA ? b1[col + 1] : 0.f;
        #pragma unroll
        for (int mi = 0; mi < 2; ++mi) {
            const int rb = m0 + wm + mi * 16;
            const int r0 = rb + g;
            const int r1 = rb + g + 8;
            if (r0 < nrows)
                *(__half2*)(g_ABh + (size_t)r0 * NCOLS + col) =
                    __floats2half2_rn(acc[mi][ni][0] + bias0, acc[mi][ni][1] + bias1);
            if (r1 < nrows)
                *(__half2*)(g_ABh + (size_t)r1 * NCOLS + col) =
                    __floats2half2_rn(acc[mi][ni][2] + bias0, acc[mi][ni][3] + bias1);
        }
    }
}

// ----------------------------------------------------------------------------
// Kernel 2: 8 edges per warp, W2 amortized in registers, 2-edge unroll.
// (exact R9 configuration — 31.3 us measured)
// ----------------------------------------------------------------------------
__device__ __forceinline__ float edge_dot(uint4 av, uint4 bv,
                                          float4 wlo, float4 whi)
{
    const __half2* a2 = (const __half2*)&av;
    const __half2* b2 = (const __half2*)&bv;
    const __half2 zero = __half2half2(__float2half(0.f));
    float2 h0 = __half22float2(__hmax2(__hadd2(a2[0], b2[0]), zero));
    float2 h1 = __half22float2(__hmax2(__hadd2(a2[1], b2[1]), zero));
    float2 h2 = __half22float2(__hmax2(__hadd2(a2[2], b2[2]), zero));
    float2 h3 = __half22float2(__hmax2(__hadd2(a2[3], b2[3]), zero));
    float s = 0.f;
    s = fmaf(h0.x, wlo.x, s);
    s = fmaf(h0.y, wlo.y, s);
    s = fmaf(h1.x, wlo.z, s);
    s = fmaf(h1.y, wlo.w, s);
    s = fmaf(h2.x, whi.x, s);
    s = fmaf(h2.y, whi.y, s);
    s = fmaf(h3.x, whi.z, s);
    s = fmaf(h3.y, whi.w, s);
    return s;
}

#define EDGES_PER_WARP 8

__global__ __launch_bounds__(256) void edge_kernel(
    const int* __restrict__ ei,
    const float* __restrict__ W2,
    const float* __restrict__ b2,
    float* __restrict__ out,
    int E)
{
    const int tid  = threadIdx.x;
    const int lane = tid & 31;
    const int warp = tid >> 5;

    const float4 wlo = __ldg((const float4*)W2 + lane * 2);
    const float4 whi = __ldg((const float4*)W2 + lane * 2 + 1);
    const float bb = __ldg(b2);

    const int base = (blockIdx.x * 8 + warp) * EDGES_PER_WARP;

    #pragma unroll
    for (int i = 0; i < EDGES_PER_WARP; i += 2) {
        const int e0 = base + i;
        const int e1 = e0 + 1;
        if (e0 >= E) return;
        const bool has1 = (e1 < E);

        const int r0 = ei[e0];
        const int c0 = ei[(size_t)E + e0];
        const int r1 = has1 ? ei[e1] : r0;
        const int c1 = has1 ? ei[(size_t)E + e1] : c0;

        const uint4 a0 = ((const uint4*)(g_ABh + (size_t)r0 * NCOLS))[lane];
        const uint4 b0 = ((const uint4*)(g_ABh + (size_t)c0 * NCOLS + HDIM))[lane];
        const uint4 a1 = ((const uint4*)(g_ABh + (size_t)r1 * NCOLS))[lane];
        const uint4 b1v = ((const uint4*)(g_ABh + (size_t)c1 * NCOLS + HDIM))[lane];

        float s0 = edge_dot(a0, b0, wlo, whi);
        float s1 = edge_dot(a1, b1v, wlo, whi);

        #pragma unroll
        for (int off = 16; off; off >>= 1) {
            s0 += __shfl_xor_sync(0xffffffff, s0, off);
            s1 += __shfl_xor_sync(0xffffffff, s1, off);
        }

        if (lane == 0)          out[e0] = 1.f / (1.f + expf(-(s0 + bb)));
        if (lane == 1 && has1)  out[e1] = 1.f / (1.f + expf(-(s1 + bb)));
    }
}

// ----------------------------------------------------------------------------
// Launch
// ----------------------------------------------------------------------------
extern "C" void kernel_launch(void* const* d_in, const int* in_sizes, int n_in,
                              void* d_out, int out_size)
{
    const float* x   = (const float*)d_in[0];
    const int*   ei  = (const int*)d_in[1];
    const float* W1  = (const float*)d_in[2];
    const float* b1  = (const float*)d_in[3];
    const float* W2  = (const float*)d_in[4];
    const float* b2  = (const float*)d_in[5];
    float*       out = (float*)d_out;

    const int Nn = in_sizes[0] / FDIM;       // 10000
    const int E  = in_sizes[1] / 2;          // 320000

    const int nX4 = Nn * (FDIM / 4);         // 640000
    const int bX  = (nX4 + 1023) / 1024;     // 625 (exact: 625*1024 = 640000)
    const int bW  = (NCOLS * (FDIM / 4)) / 1024;  // 32
    convert_kernel<<<bX + bW, 256>>>(x, W1, bX);

    dim3 ggrid((Nn + GBM - 1) / GBM, NCOLS / GBN);   // (79, 4)
    node_gemm<<<ggrid, 256>>>(b1, Nn);

    const int edges_per_block = 8 * EDGES_PER_WARP;  // 64
    const int eblocks = (E + edges_per_block - 1) / edges_per_block;  // 5000
    edge_kernel<<<eblocks, 256>>>(ei, W2, b2, out, E);
}